// round 7
// baseline (speedup 1.0000x reference)
#include <cuda_runtime.h>
#include <cuda_fp16.h>

#define N_NODES 100000
#define E_EDGES 3200000
#define HIDF    128
#define GG      64
#define BN_EPS  1e-5f
#define NB_SCAN 391   // ceil(N_NODES/256)

// ---------------- static device scratch (no runtime allocations) -------------
__device__ int   g_is64;                          // 1 if index inputs are int64
__device__ float g_dis[N_NODES];                  // rsqrt(degree)
__device__ int   g_hist[N_NODES];                 // in-degree (excl self-loop)
__device__ int   g_off[N_NODES];                  // exclusive prefix of hist
__device__ int   g_cursor[N_NODES];               // placement cursors
__device__ int   g_bsum[512];                     // block sums for scan
__device__ int   g_row[E_EDGES];
__device__ int   g_col[E_EDGES];
__device__ __align__(16) float2 g_sedge[E_EDGES];  // dest-sorted {src(bits), norm}
__device__ __align__(16) __half g_xwh[(size_t)N_NODES * HIDF]; // fp16 transformed feats
__device__ __align__(16) float g_hbuf[3u * N_NODES * HIDF];    // per-layer pre-ReLU
__device__ __align__(16) float g_Wp[3 * 2 * 64 * 64];          // BN-folded weights
__device__ __align__(16) float g_bp[3 * HIDF];                 // BN-folded bias
__device__ float g_pooled[GG * 3 * HIDF];
__device__ int   g_cnt[GG];
__device__ int   g_start[GG];

// ---------------- init + dtype detection ------------------------------------
__global__ void k_init(const int* __restrict__ ei32) {
    int i = blockIdx.x * blockDim.x + threadIdx.x;
    if (i < N_NODES) g_hist[i] = 0;
    if (i < GG) { g_cnt[i] = 0; g_start[i] = 0; }
    if (i == 0) {
        int odd_zero = 1;
        for (int k = 0; k < 64; k++)
            if (ei32[2 * k + 1] != 0) odd_zero = 0;
        g_is64 = odd_zero;   // int64 values < 2^31 have zero high words
    }
}

// edge load: -> int32 row/col, histogram over destination
__global__ void k_edge(const void* __restrict__ eiv) {
    int e = blockIdx.x * blockDim.x + threadIdx.x;
    if (e >= E_EDGES) return;
    int r, c;
    if (g_is64) {
        const long long* ei = (const long long*)eiv;
        r = (int)ei[e];
        c = (int)ei[(size_t)E_EDGES + e];
    } else {
        const int* ei = (const int*)eiv;
        r = ei[e];
        c = ei[E_EDGES + e];
    }
    g_row[e] = r;
    g_col[e] = c;
    atomicAdd(&g_hist[c], 1);
}

// ---------------- scan level 1 (+ dis = rsqrt(deg+1)) ------------------------
__global__ void __launch_bounds__(256) k_scan1() {
    __shared__ int sh[256];
    int b = blockIdx.x, t = threadIdx.x;
    int i = b * 256 + t;
    int v = (i < N_NODES) ? g_hist[i] : 0;
    if (i < N_NODES) g_dis[i] = rsqrtf((float)(v + 1));
    sh[t] = v;
    __syncthreads();
    for (int o = 1; o < 256; o <<= 1) {
        int u = (t >= o) ? sh[t - o] : 0;
        __syncthreads();
        sh[t] += u;
        __syncthreads();
    }
    if (i < N_NODES) g_off[i] = sh[t] - v;       // exclusive within block
    if (t == 255) g_bsum[b] = sh[255];
}

__global__ void __launch_bounds__(512) k_scan2() {
    __shared__ int sh[512];
    int t = threadIdx.x;
    int v = (t < NB_SCAN) ? g_bsum[t] : 0;
    sh[t] = v;
    __syncthreads();
    for (int o = 1; o < 512; o <<= 1) {
        int u = (t >= o) ? sh[t - o] : 0;
        __syncthreads();
        sh[t] += u;
        __syncthreads();
    }
    if (t < NB_SCAN) g_bsum[t] = sh[t] - v;      // exclusive block offsets
}

__global__ void k_scan3() {
    int i = blockIdx.x * blockDim.x + threadIdx.x;
    if (i >= N_NODES) return;
    int o = g_off[i] + g_bsum[i >> 8];
    g_off[i] = o;
    g_cursor[i] = o;
}

// place {src, norm} into dest-sorted order (one 8B store per edge)
__global__ void k_place() {
    int e = blockIdx.x * blockDim.x + threadIdx.x;
    if (e >= E_EDGES) return;
    int r = g_row[e];
    int c = g_col[e];
    int pos = atomicAdd(&g_cursor[c], 1);
    float nv = g_dis[r] * g_dis[c];
    g_sedge[pos] = make_float2(__int_as_float(r), nv);
}

// ---------------- BN folding -------------------------------------------------
__global__ void k_fold_w(const float* __restrict__ W, const float* __restrict__ gamma,
                         const float* __restrict__ var) {
    int idx = blockIdx.x * blockDim.x + threadIdx.x;
    if (idx >= 3 * 8192) return;
    int l = idx / 8192;
    int rem = idx - l * 8192;
    int p = rem / 4096;
    int j = rem & 63;
    int c = p * 64 + j;
    float sg = gamma[l * HIDF + c] * rsqrtf(var[l * HIDF + c] + BN_EPS);
    g_Wp[idx] = W[idx] * sg;
}

__global__ void k_fold_b(const float* __restrict__ b, const float* __restrict__ gamma,
                         const float* __restrict__ beta, const float* __restrict__ mean,
                         const float* __restrict__ var) {
    int idx = blockIdx.x * blockDim.x + threadIdx.x;
    if (idx >= 3 * HIDF) return;
    float sg = gamma[idx] * rsqrtf(var[idx] + BN_EPS);
    g_bp[idx] = b[idx] * sg + (beta[idx] - mean[idx] * sg);
}

// ---------------- block-diagonal GEMM -> fp16 xw ------------------------------
__global__ void __launch_bounds__(256) k_gemm(const float* __restrict__ x,
                                              int src_layer, int layer, int relu_in) {
    __shared__ float sW[8192];        // [2][64][64]
    __shared__ float sIn[32 * HIDF];  // 32 rows x 128
    const float* in = (src_layer < 0) ? x : (g_hbuf + (size_t)src_layer * N_NODES * HIDF);
    int t = threadIdx.x;
    const float4* Wl4 = (const float4*)(g_Wp + layer * 8192);
#pragma unroll
    for (int i = 0; i < 8; i++) {
        int idx = t + i * 256;
        ((float4*)sW)[idx] = Wl4[idx];
    }
    int R0 = blockIdx.x * 32;
#pragma unroll
    for (int i = 0; i < 4; i++) {
        int idx = t + i * 256;
        int r = idx >> 5;
        int c4 = idx & 31;
        float4 v = make_float4(0.f, 0.f, 0.f, 0.f);
        if (R0 + r < N_NODES) v = ((const float4*)in)[(size_t)(R0 + r) * 32 + c4];
        if (relu_in) {
            v.x = fmaxf(v.x, 0.f); v.y = fmaxf(v.y, 0.f);
            v.z = fmaxf(v.z, 0.f); v.w = fmaxf(v.w, 0.f);
        }
        ((float4*)sIn)[idx] = v;
    }
    __syncthreads();

    int cg = t & 31;
    int rg = t >> 5;
    int p = cg >> 4;
    int c0 = cg * 4;
    int jn = c0 & 63;
    int r0 = rg * 4;
    float acc[4][4];
#pragma unroll
    for (int i = 0; i < 4; i++) { acc[i][0] = acc[i][1] = acc[i][2] = acc[i][3] = 0.f; }
    const float* sWp = sW + p * 4096;
    const float* sInp = sIn + p * 64;
#pragma unroll 4
    for (int k = 0; k < 64; k++) {
        float4 w = *(const float4*)(sWp + k * 64 + jn);
#pragma unroll
        for (int i = 0; i < 4; i++) {
            float a = sInp[(r0 + i) * HIDF + k];
            acc[i][0] += a * w.x; acc[i][1] += a * w.y;
            acc[i][2] += a * w.z; acc[i][3] += a * w.w;
        }
    }
#pragma unroll
    for (int i = 0; i < 4; i++) {
        int r = R0 + r0 + i;
        if (r < N_NODES) {
            __half2 p0 = __floats2half2_rn(acc[i][0], acc[i][1]);
            __half2 p1 = __floats2half2_rn(acc[i][2], acc[i][3]);
            uint2 st;
            *reinterpret_cast<__half2*>(&st.x) = p0;
            *reinterpret_cast<__half2*>(&st.y) = p1;
            *reinterpret_cast<uint2*>(g_xwh + (size_t)r * HIDF + c0) = st;
        }
    }
}

// ---------------- segmented gather-reduce: one warp per destination ----------
// Inner loop unrolled x4 with batched independent gathers (raise LDG MLP).
__global__ void __launch_bounds__(256) k_aggr(int layer) {
    int node = (blockIdx.x * 256 + threadIdx.x) >> 5;
    if (node >= N_NODES) return;
    int lane = threadIdx.x & 31;
    int s0 = g_off[node];
    int s1 = (node + 1 < N_NODES) ? g_off[node + 1] : E_EDGES;
    float dc = g_dis[node];

    const uint2* __restrict__ xb = reinterpret_cast<const uint2*>(g_xwh) + lane;

    // seed: bias + self-loop (norm = dc*dc)
    float4 b = ((const float4*)g_bp)[layer * 32 + lane];
    uint2 sh = xb[(size_t)node * 32];
    float2 sa = __half22float2(*reinterpret_cast<__half2*>(&sh.x));
    float2 sb = __half22float2(*reinterpret_cast<__half2*>(&sh.y));
    float dd = dc * dc;
    float4 acc;
    acc.x = b.x + sa.x * dd; acc.y = b.y + sa.y * dd;
    acc.z = b.z + sb.x * dd; acc.w = b.w + sb.y * dd;

    for (int s = s0; s < s1; s += 32) {
        int idx = 0;
        float nv0 = 0.f;
        if (s + lane < s1) {
            float2 se = g_sedge[s + lane];
            idx = __float_as_int(se.x);
            nv0 = se.y;
        }
        int cnt = min(32, s1 - s);
        int j = 0;
        for (; j + 4 <= cnt; j += 4) {
            int r0 = __shfl_sync(0xffffffffu, idx, j);
            int r1 = __shfl_sync(0xffffffffu, idx, j + 1);
            int r2 = __shfl_sync(0xffffffffu, idx, j + 2);
            int r3 = __shfl_sync(0xffffffffu, idx, j + 3);
            float n0 = __shfl_sync(0xffffffffu, nv0, j);
            float n1 = __shfl_sync(0xffffffffu, nv0, j + 1);
            float n2 = __shfl_sync(0xffffffffu, nv0, j + 2);
            float n3 = __shfl_sync(0xffffffffu, nv0, j + 3);
            uint2 h0 = __ldg(xb + (size_t)r0 * 32);
            uint2 h1 = __ldg(xb + (size_t)r1 * 32);
            uint2 h2 = __ldg(xb + (size_t)r2 * 32);
            uint2 h3 = __ldg(xb + (size_t)r3 * 32);
            float2 a0 = __half22float2(*reinterpret_cast<__half2*>(&h0.x));
            float2 b0 = __half22float2(*reinterpret_cast<__half2*>(&h0.y));
            acc.x += a0.x * n0; acc.y += a0.y * n0; acc.z += b0.x * n0; acc.w += b0.y * n0;
            float2 a1 = __half22float2(*reinterpret_cast<__half2*>(&h1.x));
            float2 b1 = __half22float2(*reinterpret_cast<__half2*>(&h1.y));
            acc.x += a1.x * n1; acc.y += a1.y * n1; acc.z += b1.x * n1; acc.w += b1.y * n1;
            float2 a2 = __half22float2(*reinterpret_cast<__half2*>(&h2.x));
            float2 b2 = __half22float2(*reinterpret_cast<__half2*>(&h2.y));
            acc.x += a2.x * n2; acc.y += a2.y * n2; acc.z += b2.x * n2; acc.w += b2.y * n2;
            float2 a3 = __half22float2(*reinterpret_cast<__half2*>(&h3.x));
            float2 b3 = __half22float2(*reinterpret_cast<__half2*>(&h3.y));
            acc.x += a3.x * n3; acc.y += a3.y * n3; acc.z += b3.x * n3; acc.w += b3.y * n3;
        }
        for (; j < cnt; j++) {
            int r = __shfl_sync(0xffffffffu, idx, j);
            float nv = __shfl_sync(0xffffffffu, nv0, j);
            uint2 hv = __ldg(xb + (size_t)r * 32);
            float2 fa = __half22float2(*reinterpret_cast<__half2*>(&hv.x));
            float2 fb = __half22float2(*reinterpret_cast<__half2*>(&hv.y));
            acc.x += fa.x * nv; acc.y += fa.y * nv;
            acc.z += fb.x * nv; acc.w += fb.y * nv;
        }
    }
    ((float4*)(g_hbuf + (size_t)layer * N_NODES * HIDF))[(size_t)node * 32 + lane] = acc;
}

// ---------------- batch counts + segment starts (batch is sorted) ------------
__global__ void k_batch(const void* __restrict__ bv) {
    int i = blockIdx.x * blockDim.x + threadIdx.x;
    if (i >= N_NODES) return;
    int b, bp = -1;
    if (g_is64) {
        const long long* bb = (const long long*)bv;
        b = (int)bb[i];
        if (i > 0) bp = (int)bb[i - 1];
    } else {
        const int* bb = (const int*)bv;
        b = bb[i];
        if (i > 0) bp = bb[i - 1];
    }
    atomicAdd(&g_cnt[b], 1);
    if (i == 0 || bp != b) g_start[b] = i;
}

// ---------------- mean pool with lazy ReLU -----------------------------------
__global__ void __launch_bounds__(128) k_pool() {
    int g = blockIdx.x;
    int l = blockIdx.y;
    int t = threadIdx.x;
    int s = g_start[g];
    int n = g_cnt[g];
    const float* base = g_hbuf + ((size_t)l * N_NODES + s) * HIDF + t;
    float acc = 0.f;
    for (int j = 0; j < n; j++) acc += fmaxf(base[(size_t)j * HIDF], 0.f);
    g_pooled[g * (3 * HIDF) + l * HIDF + t] = acc / fmaxf((float)n, 1.f);
}

// ---------------- MLP head + log_softmax -------------------------------------
__global__ void __launch_bounds__(128) k_head(const float* __restrict__ Wfc1,
                                              const float* __restrict__ bfc1,
                                              const float* __restrict__ Wfc2,
                                              const float* __restrict__ bfc2,
                                              float* __restrict__ out) {
    __shared__ float sP[3 * HIDF];
    __shared__ float sH[HIDF];
    __shared__ float sZ[2];
    int g = blockIdx.x;
    int t = threadIdx.x;
    for (int i = t; i < 3 * HIDF; i += 128) sP[i] = g_pooled[g * (3 * HIDF) + i];
    __syncthreads();
    float acc = bfc1[t];
#pragma unroll 8
    for (int k = 0; k < 3 * HIDF; k++) acc += sP[k] * Wfc1[k * HIDF + t];
    sH[t] = fmaxf(acc, 0.f);
    __syncthreads();
    if (t < 2) {
        float z = bfc2[t];
#pragma unroll 8
        for (int j = 0; j < HIDF; j++) z += sH[j] * Wfc2[j * 2 + t];
        sZ[t] = z;
    }
    __syncthreads();
    if (t == 0) {
        float z0 = sZ[0], z1 = sZ[1];
        float m = fmaxf(z0, z1);
        float lse = m + logf(expf(z0 - m) + expf(z1 - m));
        out[g * 2 + 0] = z0 - lse;
        out[g * 2 + 1] = z1 - lse;
    }
}

// ---------------- driver ------------------------------------------------------
extern "C" void kernel_launch(void* const* d_in, const int* in_sizes, int n_in,
                              void* d_out, int out_size) {
    const float* x        = (const float*)d_in[0];
    const void*  ei       = d_in[1];
    const void*  bat      = d_in[2];
    const float* W_conv   = (const float*)d_in[3];
    const float* b_conv   = (const float*)d_in[4];
    const float* bn_gamma = (const float*)d_in[5];
    const float* bn_beta  = (const float*)d_in[6];
    const float* bn_mean  = (const float*)d_in[7];
    const float* bn_var   = (const float*)d_in[8];
    const float* W_fc1    = (const float*)d_in[9];
    const float* b_fc1    = (const float*)d_in[10];
    const float* W_fc2    = (const float*)d_in[11];
    const float* b_fc2    = (const float*)d_in[12];
    float* out = (float*)d_out;

    k_init<<<(N_NODES + 255) / 256, 256>>>((const int*)ei);
    k_edge<<<(E_EDGES + 255) / 256, 256>>>(ei);
    k_scan1<<<NB_SCAN, 256>>>();
    k_scan2<<<1, 512>>>();
    k_scan3<<<(N_NODES + 255) / 256, 256>>>();
    k_place<<<(E_EDGES + 255) / 256, 256>>>();
    k_fold_w<<<(3 * 8192 + 255) / 256, 256>>>(W_conv, bn_gamma, bn_var);
    k_fold_b<<<2, 256>>>(b_conv, bn_gamma, bn_beta, bn_mean, bn_var);

    for (int l = 0; l < 3; l++) {
        k_gemm<<<(N_NODES + 31) / 32, 256>>>(x, l - 1, l, (l > 0) ? 1 : 0);
        k_aggr<<<(N_NODES * 32 + 255) / 256, 256>>>(l);
    }

    k_batch<<<(N_NODES + 255) / 256, 256>>>(bat);
    dim3 pg(GG, 3);
    k_pool<<<pg, 128>>>();
    k_head<<<GG, 128>>>(W_fc1, b_fc1, W_fc2, b_fc2, out);
}

// round 8
// speedup vs baseline: 1.3306x; 1.3306x over previous
#include <cuda_runtime.h>
#include <cuda_fp16.h>

#define N_NODES 100000
#define E_EDGES 3200000
#define HIDF    128
#define GG      64
#define BN_EPS  1e-5f
#define NB_SCAN 391   // ceil(N_NODES/256)

// ---------------- static device scratch (no runtime allocations) -------------
__device__ int   g_is64;                          // 1 if index inputs are int64
__device__ float g_dis[N_NODES];                  // rsqrt(degree)
__device__ int   g_hist[N_NODES];                 // in-degree (excl self-loop)
__device__ int   g_off[N_NODES];                  // exclusive prefix of hist
__device__ int   g_cursor[N_NODES];               // placement cursors
__device__ int   g_bsum[512];                     // block sums for scan
__device__ int   g_row[E_EDGES];
__device__ int   g_col[E_EDGES];
__device__ __align__(16) float2 g_sedge[E_EDGES];  // dest-sorted {src(bits), norm}
__device__ __align__(16) __half g_xwh[(size_t)N_NODES * HIDF]; // fp16 transformed feats
__device__ __align__(16) float g_hbuf[3u * N_NODES * HIDF];    // per-layer pre-ReLU
__device__ __align__(16) float g_Wp[3 * 2 * 64 * 64];          // BN-folded weights
__device__ __align__(16) float g_bp[3 * HIDF];                 // BN-folded bias
__device__ float g_pooled[GG * 3 * HIDF];
__device__ int   g_cnt[GG];
__device__ int   g_start[GG];

// ---------------- init + dtype detection ------------------------------------
__global__ void k_init(const int* __restrict__ ei32) {
    int i = blockIdx.x * blockDim.x + threadIdx.x;
    if (i < N_NODES) g_hist[i] = 0;
    if (i < GG) { g_cnt[i] = 0; g_start[i] = 0; }
    if (i == 0) {
        int odd_zero = 1;
        for (int k = 0; k < 64; k++)
            if (ei32[2 * k + 1] != 0) odd_zero = 0;
        g_is64 = odd_zero;   // int64 values < 2^31 have zero high words
    }
}

// edge load: -> int32 row/col, histogram over destination
__global__ void k_edge(const void* __restrict__ eiv) {
    int e = blockIdx.x * blockDim.x + threadIdx.x;
    if (e >= E_EDGES) return;
    int r, c;
    if (g_is64) {
        const long long* ei = (const long long*)eiv;
        r = (int)ei[e];
        c = (int)ei[(size_t)E_EDGES + e];
    } else {
        const int* ei = (const int*)eiv;
        r = ei[e];
        c = ei[E_EDGES + e];
    }
    g_row[e] = r;
    g_col[e] = c;
    atomicAdd(&g_hist[c], 1);
}

// ---------------- scan level 1 (+ dis = rsqrt(deg+1)) ------------------------
__global__ void __launch_bounds__(256) k_scan1() {
    __shared__ int sh[256];
    int b = blockIdx.x, t = threadIdx.x;
    int i = b * 256 + t;
    int v = (i < N_NODES) ? g_hist[i] : 0;
    if (i < N_NODES) g_dis[i] = rsqrtf((float)(v + 1));
    sh[t] = v;
    __syncthreads();
    for (int o = 1; o < 256; o <<= 1) {
        int u = (t >= o) ? sh[t - o] : 0;
        __syncthreads();
        sh[t] += u;
        __syncthreads();
    }
    if (i < N_NODES) g_off[i] = sh[t] - v;       // exclusive within block
    if (t == 255) g_bsum[b] = sh[255];
}

__global__ void __launch_bounds__(512) k_scan2() {
    __shared__ int sh[512];
    int t = threadIdx.x;
    int v = (t < NB_SCAN) ? g_bsum[t] : 0;
    sh[t] = v;
    __syncthreads();
    for (int o = 1; o < 512; o <<= 1) {
        int u = (t >= o) ? sh[t - o] : 0;
        __syncthreads();
        sh[t] += u;
        __syncthreads();
    }
    if (t < NB_SCAN) g_bsum[t] = sh[t] - v;      // exclusive block offsets
}

__global__ void k_scan3() {
    int i = blockIdx.x * blockDim.x + threadIdx.x;
    if (i >= N_NODES) return;
    int o = g_off[i] + g_bsum[i >> 8];
    g_off[i] = o;
    g_cursor[i] = o;
}

// place {src, norm} into dest-sorted order (one 8B store per edge)
__global__ void k_place() {
    int e = blockIdx.x * blockDim.x + threadIdx.x;
    if (e >= E_EDGES) return;
    int r = g_row[e];
    int c = g_col[e];
    int pos = atomicAdd(&g_cursor[c], 1);
    float nv = g_dis[r] * g_dis[c];
    g_sedge[pos] = make_float2(__int_as_float(r), nv);
}

// ---------------- BN folding -------------------------------------------------
__global__ void k_fold_w(const float* __restrict__ W, const float* __restrict__ gamma,
                         const float* __restrict__ var) {
    int idx = blockIdx.x * blockDim.x + threadIdx.x;
    if (idx >= 3 * 8192) return;
    int l = idx / 8192;
    int rem = idx - l * 8192;
    int p = rem / 4096;
    int j = rem & 63;
    int c = p * 64 + j;
    float sg = gamma[l * HIDF + c] * rsqrtf(var[l * HIDF + c] + BN_EPS);
    g_Wp[idx] = W[idx] * sg;
}

__global__ void k_fold_b(const float* __restrict__ b, const float* __restrict__ gamma,
                         const float* __restrict__ beta, const float* __restrict__ mean,
                         const float* __restrict__ var) {
    int idx = blockIdx.x * blockDim.x + threadIdx.x;
    if (idx >= 3 * HIDF) return;
    float sg = gamma[idx] * rsqrtf(var[idx] + BN_EPS);
    g_bp[idx] = b[idx] * sg + (beta[idx] - mean[idx] * sg);
}

// ---------------- block-diagonal GEMM -> fp16 xw ------------------------------
__global__ void __launch_bounds__(256) k_gemm(const float* __restrict__ x,
                                              int src_layer, int layer, int relu_in) {
    __shared__ float sW[8192];        // [2][64][64]
    __shared__ float sIn[32 * HIDF];  // 32 rows x 128
    const float* in = (src_layer < 0) ? x : (g_hbuf + (size_t)src_layer * N_NODES * HIDF);
    int t = threadIdx.x;
    const float4* Wl4 = (const float4*)(g_Wp + layer * 8192);
#pragma unroll
    for (int i = 0; i < 8; i++) {
        int idx = t + i * 256;
        ((float4*)sW)[idx] = Wl4[idx];
    }
    int R0 = blockIdx.x * 32;
#pragma unroll
    for (int i = 0; i < 4; i++) {
        int idx = t + i * 256;
        int r = idx >> 5;
        int c4 = idx & 31;
        float4 v = make_float4(0.f, 0.f, 0.f, 0.f);
        if (R0 + r < N_NODES) v = ((const float4*)in)[(size_t)(R0 + r) * 32 + c4];
        if (relu_in) {
            v.x = fmaxf(v.x, 0.f); v.y = fmaxf(v.y, 0.f);
            v.z = fmaxf(v.z, 0.f); v.w = fmaxf(v.w, 0.f);
        }
        ((float4*)sIn)[idx] = v;
    }
    __syncthreads();

    int cg = t & 31;
    int rg = t >> 5;
    int p = cg >> 4;
    int c0 = cg * 4;
    int jn = c0 & 63;
    int r0 = rg * 4;
    float acc[4][4];
#pragma unroll
    for (int i = 0; i < 4; i++) { acc[i][0] = acc[i][1] = acc[i][2] = acc[i][3] = 0.f; }
    const float* sWp = sW + p * 4096;
    const float* sInp = sIn + p * 64;
#pragma unroll 4
    for (int k = 0; k < 64; k++) {
        float4 w = *(const float4*)(sWp + k * 64 + jn);
#pragma unroll
        for (int i = 0; i < 4; i++) {
            float a = sInp[(r0 + i) * HIDF + k];
            acc[i][0] += a * w.x; acc[i][1] += a * w.y;
            acc[i][2] += a * w.z; acc[i][3] += a * w.w;
        }
    }
#pragma unroll
    for (int i = 0; i < 4; i++) {
        int r = R0 + r0 + i;
        if (r < N_NODES) {
            __half2 p0 = __floats2half2_rn(acc[i][0], acc[i][1]);
            __half2 p1 = __floats2half2_rn(acc[i][2], acc[i][3]);
            uint2 st;
            *reinterpret_cast<__half2*>(&st.x) = p0;
            *reinterpret_cast<__half2*>(&st.y) = p1;
            *reinterpret_cast<uint2*>(g_xwh + (size_t)r * HIDF + c0) = st;
        }
    }
}

// ---------------- segmented gather-reduce: one warp per node, 2 edges/iter ---
// 16 lanes per feature row (uint4 = 8 halves each); half-warp g handles edge
// (lane&16)+j of each 32-edge chunk. Invalid edges carry norm=0.
__global__ void __launch_bounds__(256) k_aggr(int layer) {
    int node = (blockIdx.x * 256 + threadIdx.x) >> 5;
    if (node >= N_NODES) return;
    int lane = threadIdx.x & 31;
    int lg = lane & 15;            // lane within half-warp
    int gsel = lane & 16;          // 0 or 16
    int s0 = g_off[node];
    int s1 = (node + 1 < N_NODES) ? g_off[node + 1] : E_EDGES;

    const uint4* xb = reinterpret_cast<const uint4*>(g_xwh);   // row r -> xb[r*16+lg]

    float acc[8];
#pragma unroll
    for (int k = 0; k < 8; k++) acc[k] = 0.f;
    if (gsel == 0) {
        // seed: bias + self-loop (norm = dc*dc)
        float dc = g_dis[node];
        float dd = dc * dc;
        float4 b0 = ((const float4*)g_bp)[layer * 32 + lg * 2];
        float4 b1 = ((const float4*)g_bp)[layer * 32 + lg * 2 + 1];
        uint4 sv = xb[(size_t)node * 16 + lg];
        float2 f0 = __half22float2(*reinterpret_cast<__half2*>(&sv.x));
        float2 f1 = __half22float2(*reinterpret_cast<__half2*>(&sv.y));
        float2 f2 = __half22float2(*reinterpret_cast<__half2*>(&sv.z));
        float2 f3 = __half22float2(*reinterpret_cast<__half2*>(&sv.w));
        acc[0] = b0.x + f0.x * dd; acc[1] = b0.y + f0.y * dd;
        acc[2] = b0.z + f1.x * dd; acc[3] = b0.w + f1.y * dd;
        acc[4] = b1.x + f2.x * dd; acc[5] = b1.y + f2.y * dd;
        acc[6] = b1.z + f3.x * dd; acc[7] = b1.w + f3.y * dd;
    }

    for (int s = s0; s < s1; s += 32) {
        int idx = 0;
        float nv0 = 0.f;
        if (s + lane < s1) {
            float2 se = g_sedge[s + lane];
            idx = __float_as_int(se.x);
            nv0 = se.y;
        }
        int jmax = min(16, s1 - s);
        for (int j = 0; j < jmax; j++) {
            int r = __shfl_sync(0xffffffffu, idx, gsel + j);
            float nv = __shfl_sync(0xffffffffu, nv0, gsel + j);
            uint4 hv = __ldg(xb + (size_t)r * 16 + lg);
            float2 f0 = __half22float2(*reinterpret_cast<__half2*>(&hv.x));
            float2 f1 = __half22float2(*reinterpret_cast<__half2*>(&hv.y));
            float2 f2 = __half22float2(*reinterpret_cast<__half2*>(&hv.z));
            float2 f3 = __half22float2(*reinterpret_cast<__half2*>(&hv.w));
            acc[0] += f0.x * nv; acc[1] += f0.y * nv;
            acc[2] += f1.x * nv; acc[3] += f1.y * nv;
            acc[4] += f2.x * nv; acc[5] += f2.y * nv;
            acc[6] += f3.x * nv; acc[7] += f3.y * nv;
        }
    }

    // combine the two half-warps, then each half stores one float4
#pragma unroll
    for (int k = 0; k < 8; k++) acc[k] += __shfl_xor_sync(0xffffffffu, acc[k], 16);
    float* dst = g_hbuf + (size_t)layer * N_NODES * HIDF + (size_t)node * HIDF
               + lg * 8 + (gsel ? 4 : 0);
    *(float4*)dst = gsel ? make_float4(acc[4], acc[5], acc[6], acc[7])
                         : make_float4(acc[0], acc[1], acc[2], acc[3]);
}

// ---------------- batch counts + segment starts (batch is sorted) ------------
__global__ void k_batch(const void* __restrict__ bv) {
    int i = blockIdx.x * blockDim.x + threadIdx.x;
    if (i >= N_NODES) return;
    int b, bp = -1;
    if (g_is64) {
        const long long* bb = (const long long*)bv;
        b = (int)bb[i];
        if (i > 0) bp = (int)bb[i - 1];
    } else {
        const int* bb = (const int*)bv;
        b = bb[i];
        if (i > 0) bp = bb[i - 1];
    }
    atomicAdd(&g_cnt[b], 1);
    if (i == 0 || bp != b) g_start[b] = i;
}

// ---------------- mean pool with lazy ReLU -----------------------------------
__global__ void __launch_bounds__(128) k_pool() {
    int g = blockIdx.x;
    int l = blockIdx.y;
    int t = threadIdx.x;
    int s = g_start[g];
    int n = g_cnt[g];
    const float* base = g_hbuf + ((size_t)l * N_NODES + s) * HIDF + t;
    float acc = 0.f;
    for (int j = 0; j < n; j++) acc += fmaxf(base[(size_t)j * HIDF], 0.f);
    g_pooled[g * (3 * HIDF) + l * HIDF + t] = acc / fmaxf((float)n, 1.f);
}

// ---------------- MLP head + log_softmax -------------------------------------
__global__ void __launch_bounds__(128) k_head(const float* __restrict__ Wfc1,
                                              const float* __restrict__ bfc1,
                                              const float* __restrict__ Wfc2,
                                              const float* __restrict__ bfc2,
                                              float* __restrict__ out) {
    __shared__ float sP[3 * HIDF];
    __shared__ float sH[HIDF];
    __shared__ float sZ[2];
    int g = blockIdx.x;
    int t = threadIdx.x;
    for (int i = t; i < 3 * HIDF; i += 128) sP[i] = g_pooled[g * (3 * HIDF) + i];
    __syncthreads();
    float acc = bfc1[t];
#pragma unroll 8
    for (int k = 0; k < 3 * HIDF; k++) acc += sP[k] * Wfc1[k * HIDF + t];
    sH[t] = fmaxf(acc, 0.f);
    __syncthreads();
    if (t < 2) {
        float z = bfc2[t];
#pragma unroll 8
        for (int j = 0; j < HIDF; j++) z += sH[j] * Wfc2[j * 2 + t];
        sZ[t] = z;
    }
    __syncthreads();
    if (t == 0) {
        float z0 = sZ[0], z1 = sZ[1];
        float m = fmaxf(z0, z1);
        float lse = m + logf(expf(z0 - m) + expf(z1 - m));
        out[g * 2 + 0] = z0 - lse;
        out[g * 2 + 1] = z1 - lse;
    }
}

// ---------------- driver ------------------------------------------------------
extern "C" void kernel_launch(void* const* d_in, const int* in_sizes, int n_in,
                              void* d_out, int out_size) {
    const float* x        = (const float*)d_in[0];
    const void*  ei       = d_in[1];
    const void*  bat      = d_in[2];
    const float* W_conv   = (const float*)d_in[3];
    const float* b_conv   = (const float*)d_in[4];
    const float* bn_gamma = (const float*)d_in[5];
    const float* bn_beta  = (const float*)d_in[6];
    const float* bn_mean  = (const float*)d_in[7];
    const float* bn_var   = (const float*)d_in[8];
    const float* W_fc1    = (const float*)d_in[9];
    const float* b_fc1    = (const float*)d_in[10];
    const float* W_fc2    = (const float*)d_in[11];
    const float* b_fc2    = (const float*)d_in[12];
    float* out = (float*)d_out;

    k_init<<<(N_NODES + 255) / 256, 256>>>((const int*)ei);
    k_edge<<<(E_EDGES + 255) / 256, 256>>>(ei);
    k_scan1<<<NB_SCAN, 256>>>();
    k_scan2<<<1, 512>>>();
    k_scan3<<<(N_NODES + 255) / 256, 256>>>();
    k_place<<<(E_EDGES + 255) / 256, 256>>>();
    k_fold_w<<<(3 * 8192 + 255) / 256, 256>>>(W_conv, bn_gamma, bn_var);
    k_fold_b<<<2, 256>>>(b_conv, bn_gamma, bn_beta, bn_mean, bn_var);

    for (int l = 0; l < 3; l++) {
        k_gemm<<<(N_NODES + 31) / 32, 256>>>(x, l - 1, l, (l > 0) ? 1 : 0);
        k_aggr<<<(N_NODES * 32 + 255) / 256, 256>>>(l);
    }

    k_batch<<<(N_NODES + 255) / 256, 256>>>(bat);
    dim3 pg(GG, 3);
    k_pool<<<pg, 128>>>();
    k_head<<<GG, 128>>>(W_fc1, b_fc1, W_fc2, b_fc2, out);
}

// round 9
// speedup vs baseline: 1.4532x; 1.0921x over previous
#include <cuda_runtime.h>
#include <cuda_fp16.h>
#include <cuda_fp8.h>

#define N_NODES 100000
#define E_EDGES 3200000
#define HIDF    128
#define GG      64
#define BN_EPS  1e-5f
#define NB_SCAN 391   // ceil(N_NODES/256)

// ---------------- static device scratch (no runtime allocations) -------------
__device__ int   g_is64;                          // 1 if index inputs are int64
__device__ float g_dis[N_NODES];                  // rsqrt(degree)
__device__ int   g_hist[N_NODES];                 // in-degree (excl self-loop)
__device__ int   g_off[N_NODES];                  // exclusive prefix of hist
__device__ int   g_cursor[N_NODES];               // placement cursors
__device__ int   g_bsum[512];                     // block sums for scan
__device__ int   g_row[E_EDGES];
__device__ int   g_col[E_EDGES];
__device__ __align__(16) float2 g_sedge[E_EDGES];  // dest-sorted {src(bits), norm}
__device__ __align__(16) unsigned g_xf8[(size_t)N_NODES * 32];  // fp8 e4m3 feats (128B/row)
__device__ __align__(16) __half g_hbuf[3u * N_NODES * HIDF];    // per-layer pre-ReLU (fp16)
__device__ __align__(16) float g_Wp[3 * 2 * 64 * 64];          // BN-folded weights
__device__ __align__(16) float g_bp[3 * HIDF];                 // BN-folded bias
__device__ float g_pooled[GG * 3 * HIDF];
__device__ int   g_cnt[GG];
__device__ int   g_start[GG];

// fp8x2 (e4m3) -> float2
static __device__ __forceinline__ float2 fp8x2_to_f2(unsigned short v) {
    __half2_raw hr = __nv_cvt_fp8x2_to_halfraw2((__nv_fp8x2_storage_t)v, __NV_E4M3);
    return __half22float2(*reinterpret_cast<__half2*>(&hr));
}
// float2 -> fp8x2 (e4m3)
static __device__ __forceinline__ unsigned short f2_to_fp8x2(float a, float b) {
    return (unsigned short)__nv_cvt_float2_to_fp8x2(make_float2(a, b), __NV_SATFINITE, __NV_E4M3);
}

// ---------------- init + dtype detection ------------------------------------
__global__ void k_init(const int* __restrict__ ei32) {
    int i = blockIdx.x * blockDim.x + threadIdx.x;
    if (i < N_NODES) g_hist[i] = 0;
    if (i < GG) { g_cnt[i] = 0; g_start[i] = 0; }
    if (i == 0) {
        int odd_zero = 1;
        for (int k = 0; k < 64; k++)
            if (ei32[2 * k + 1] != 0) odd_zero = 0;
        g_is64 = odd_zero;   // int64 values < 2^31 have zero high words
    }
}

// edge load: -> int32 row/col, histogram over destination
__global__ void k_edge(const void* __restrict__ eiv) {
    int e = blockIdx.x * blockDim.x + threadIdx.x;
    if (e >= E_EDGES) return;
    int r, c;
    if (g_is64) {
        const long long* ei = (const long long*)eiv;
        r = (int)ei[e];
        c = (int)ei[(size_t)E_EDGES + e];
    } else {
        const int* ei = (const int*)eiv;
        r = ei[e];
        c = ei[E_EDGES + e];
    }
    g_row[e] = r;
    g_col[e] = c;
    atomicAdd(&g_hist[c], 1);
}

// ---------------- scan level 1 (+ dis = rsqrt(deg+1)) ------------------------
__global__ void __launch_bounds__(256) k_scan1() {
    __shared__ int sh[256];
    int b = blockIdx.x, t = threadIdx.x;
    int i = b * 256 + t;
    int v = (i < N_NODES) ? g_hist[i] : 0;
    if (i < N_NODES) g_dis[i] = rsqrtf((float)(v + 1));
    sh[t] = v;
    __syncthreads();
    for (int o = 1; o < 256; o <<= 1) {
        int u = (t >= o) ? sh[t - o] : 0;
        __syncthreads();
        sh[t] += u;
        __syncthreads();
    }
    if (i < N_NODES) g_off[i] = sh[t] - v;       // exclusive within block
    if (t == 255) g_bsum[b] = sh[255];
}

__global__ void __launch_bounds__(512) k_scan2() {
    __shared__ int sh[512];
    int t = threadIdx.x;
    int v = (t < NB_SCAN) ? g_bsum[t] : 0;
    sh[t] = v;
    __syncthreads();
    for (int o = 1; o < 512; o <<= 1) {
        int u = (t >= o) ? sh[t - o] : 0;
        __syncthreads();
        sh[t] += u;
        __syncthreads();
    }
    if (t < NB_SCAN) g_bsum[t] = sh[t] - v;      // exclusive block offsets
}

__global__ void k_scan3() {
    int i = blockIdx.x * blockDim.x + threadIdx.x;
    if (i >= N_NODES) return;
    int o = g_off[i] + g_bsum[i >> 8];
    g_off[i] = o;
    g_cursor[i] = o;
}

// place {src, norm} into dest-sorted order (one 8B store per edge)
__global__ void k_place() {
    int e = blockIdx.x * blockDim.x + threadIdx.x;
    if (e >= E_EDGES) return;
    int r = g_row[e];
    int c = g_col[e];
    int pos = atomicAdd(&g_cursor[c], 1);
    float nv = g_dis[r] * g_dis[c];
    g_sedge[pos] = make_float2(__int_as_float(r), nv);
}

// ---------------- BN folding -------------------------------------------------
__global__ void k_fold_w(const float* __restrict__ W, const float* __restrict__ gamma,
                         const float* __restrict__ var) {
    int idx = blockIdx.x * blockDim.x + threadIdx.x;
    if (idx >= 3 * 8192) return;
    int l = idx / 8192;
    int rem = idx - l * 8192;
    int p = rem / 4096;
    int j = rem & 63;
    int c = p * 64 + j;
    float sg = gamma[l * HIDF + c] * rsqrtf(var[l * HIDF + c] + BN_EPS);
    g_Wp[idx] = W[idx] * sg;
}

__global__ void k_fold_b(const float* __restrict__ b, const float* __restrict__ gamma,
                         const float* __restrict__ beta, const float* __restrict__ mean,
                         const float* __restrict__ var) {
    int idx = blockIdx.x * blockDim.x + threadIdx.x;
    if (idx >= 3 * HIDF) return;
    float sg = gamma[idx] * rsqrtf(var[idx] + BN_EPS);
    g_bp[idx] = b[idx] * sg + (beta[idx] - mean[idx] * sg);
}

// ---------------- block-diagonal GEMM -> fp8 xw table -------------------------
// Layer 0 input: fp32 x. Layers 1,2 input: fp16 hbuf (+ReLU).
__global__ void __launch_bounds__(256) k_gemm(const float* __restrict__ x,
                                              int src_layer, int layer, int relu_in) {
    __shared__ float sW[8192];        // [2][64][64]
    __shared__ float sIn[32 * HIDF];  // 32 rows x 128
    int t = threadIdx.x;
    const float4* Wl4 = (const float4*)(g_Wp + layer * 8192);
#pragma unroll
    for (int i = 0; i < 8; i++) {
        int idx = t + i * 256;
        ((float4*)sW)[idx] = Wl4[idx];
    }
    int R0 = blockIdx.x * 32;
    if (src_layer < 0) {
#pragma unroll
        for (int i = 0; i < 4; i++) {
            int idx = t + i * 256;
            int r = idx >> 5;
            int c4 = idx & 31;
            float4 v = make_float4(0.f, 0.f, 0.f, 0.f);
            if (R0 + r < N_NODES) v = ((const float4*)x)[(size_t)(R0 + r) * 32 + c4];
            ((float4*)sIn)[idx] = v;
        }
    } else {
        const uint2* hb = reinterpret_cast<const uint2*>(
            g_hbuf + (size_t)src_layer * N_NODES * HIDF);
#pragma unroll
        for (int i = 0; i < 4; i++) {
            int idx = t + i * 256;
            int r = idx >> 5;
            int c4 = idx & 31;
            float4 v = make_float4(0.f, 0.f, 0.f, 0.f);
            if (R0 + r < N_NODES) {
                uint2 hw = hb[(size_t)(R0 + r) * 32 + c4];
                float2 f0 = __half22float2(*reinterpret_cast<__half2*>(&hw.x));
                float2 f1 = __half22float2(*reinterpret_cast<__half2*>(&hw.y));
                v = make_float4(fmaxf(f0.x, 0.f), fmaxf(f0.y, 0.f),
                                fmaxf(f1.x, 0.f), fmaxf(f1.y, 0.f));
            }
            ((float4*)sIn)[idx] = v;
        }
    }
    __syncthreads();

    int cg = t & 31;
    int rg = t >> 5;
    int p = cg >> 4;
    int c0 = cg * 4;
    int jn = c0 & 63;
    int r0 = rg * 4;
    float acc[4][4];
#pragma unroll
    for (int i = 0; i < 4; i++) { acc[i][0] = acc[i][1] = acc[i][2] = acc[i][3] = 0.f; }
    const float* sWp = sW + p * 4096;
    const float* sInp = sIn + p * 64;
#pragma unroll 4
    for (int k = 0; k < 64; k++) {
        float4 w = *(const float4*)(sWp + k * 64 + jn);
#pragma unroll
        for (int i = 0; i < 4; i++) {
            float a = sInp[(r0 + i) * HIDF + k];
            acc[i][0] += a * w.x; acc[i][1] += a * w.y;
            acc[i][2] += a * w.z; acc[i][3] += a * w.w;
        }
    }
#pragma unroll
    for (int i = 0; i < 4; i++) {
        int r = R0 + r0 + i;
        if (r < N_NODES) {
            unsigned lo = f2_to_fp8x2(acc[i][0], acc[i][1]);
            unsigned hi = f2_to_fp8x2(acc[i][2], acc[i][3]);
            g_xf8[(size_t)r * 32 + cg] = lo | (hi << 16);
        }
    }
}

// ---------------- segmented gather-reduce: one warp per destination ----------
// Row = 128 fp8 = 128B; lane loads one uint (4 fp8). Rolled inner loop.
__global__ void __launch_bounds__(256) k_aggr(int layer) {
    int node = (blockIdx.x * 256 + threadIdx.x) >> 5;
    if (node >= N_NODES) return;
    int lane = threadIdx.x & 31;
    int s0 = g_off[node];
    int s1 = (node + 1 < N_NODES) ? g_off[node + 1] : E_EDGES;
    float dc = g_dis[node];

    const unsigned* __restrict__ xb = g_xf8 + lane;

    // seed: bias + self-loop (norm = dc*dc)
    float4 b = ((const float4*)g_bp)[layer * 32 + lane];
    unsigned sw = xb[(size_t)node * 32];
    float2 sa = fp8x2_to_f2((unsigned short)(sw & 0xffffu));
    float2 sb = fp8x2_to_f2((unsigned short)(sw >> 16));
    float dd = dc * dc;
    float4 acc;
    acc.x = b.x + sa.x * dd; acc.y = b.y + sa.y * dd;
    acc.z = b.z + sb.x * dd; acc.w = b.w + sb.y * dd;

    for (int s = s0; s < s1; s += 32) {
        int idx = 0;
        float nv0 = 0.f;
        if (s + lane < s1) {
            float2 se = g_sedge[s + lane];
            idx = __float_as_int(se.x);
            nv0 = se.y;
        }
        int cnt = min(32, s1 - s);
        for (int j = 0; j < cnt; j++) {
            int r = __shfl_sync(0xffffffffu, idx, j);
            float nv = __shfl_sync(0xffffffffu, nv0, j);
            unsigned w = __ldg(xb + (size_t)r * 32);
            float2 fa = fp8x2_to_f2((unsigned short)(w & 0xffffu));
            float2 fb = fp8x2_to_f2((unsigned short)(w >> 16));
            acc.x += fa.x * nv; acc.y += fa.y * nv;
            acc.z += fb.x * nv; acc.w += fb.y * nv;
        }
    }
    // store fp16 hbuf: 4 halves (8B) per lane
    __half2 h0 = __floats2half2_rn(acc.x, acc.y);
    __half2 h1 = __floats2half2_rn(acc.z, acc.w);
    uint2 st;
    *reinterpret_cast<__half2*>(&st.x) = h0;
    *reinterpret_cast<__half2*>(&st.y) = h1;
    reinterpret_cast<uint2*>(g_hbuf + (size_t)layer * N_NODES * HIDF)[(size_t)node * 32 + lane] = st;
}

// ---------------- batch counts + segment starts (batch is sorted) ------------
__global__ void k_batch(const void* __restrict__ bv) {
    int i = blockIdx.x * blockDim.x + threadIdx.x;
    if (i >= N_NODES) return;
    int b, bp = -1;
    if (g_is64) {
        const long long* bb = (const long long*)bv;
        b = (int)bb[i];
        if (i > 0) bp = (int)bb[i - 1];
    } else {
        const int* bb = (const int*)bv;
        b = bb[i];
        if (i > 0) bp = bb[i - 1];
    }
    atomicAdd(&g_cnt[b], 1);
    if (i == 0 || bp != b) g_start[b] = i;
}

// ---------------- mean pool with lazy ReLU (fp16 hbuf) -----------------------
__global__ void __launch_bounds__(128) k_pool() {
    int g = blockIdx.x;
    int l = blockIdx.y;
    int t = threadIdx.x;
    int s = g_start[g];
    int n = g_cnt[g];
    const __half* base = g_hbuf + ((size_t)l * N_NODES + s) * HIDF + t;
    float acc = 0.f;
    for (int j = 0; j < n; j++) acc += fmaxf(__half2float(base[(size_t)j * HIDF]), 0.f);
    g_pooled[g * (3 * HIDF) + l * HIDF + t] = acc / fmaxf((float)n, 1.f);
}

// ---------------- MLP head + log_softmax -------------------------------------
__global__ void __launch_bounds__(128) k_head(const float* __restrict__ Wfc1,
                                              const float* __restrict__ bfc1,
                                              const float* __restrict__ Wfc2,
                                              const float* __restrict__ bfc2,
                                              float* __restrict__ out) {
    __shared__ float sP[3 * HIDF];
    __shared__ float sH[HIDF];
    __shared__ float sZ[2];
    int g = blockIdx.x;
    int t = threadIdx.x;
    for (int i = t; i < 3 * HIDF; i += 128) sP[i] = g_pooled[g * (3 * HIDF) + i];
    __syncthreads();
    float acc = bfc1[t];
#pragma unroll 8
    for (int k = 0; k < 3 * HIDF; k++) acc += sP[k] * Wfc1[k * HIDF + t];
    sH[t] = fmaxf(acc, 0.f);
    __syncthreads();
    if (t < 2) {
        float z = bfc2[t];
#pragma unroll 8
        for (int j = 0; j < HIDF; j++) z += sH[j] * Wfc2[j * 2 + t];
        sZ[t] = z;
    }
    __syncthreads();
    if (t == 0) {
        float z0 = sZ[0], z1 = sZ[1];
        float m = fmaxf(z0, z1);
        float lse = m + logf(expf(z0 - m) + expf(z1 - m));
        out[g * 2 + 0] = z0 - lse;
        out[g * 2 + 1] = z1 - lse;
    }
}

// ---------------- driver ------------------------------------------------------
extern "C" void kernel_launch(void* const* d_in, const int* in_sizes, int n_in,
                              void* d_out, int out_size) {
    const float* x        = (const float*)d_in[0];
    const void*  ei       = d_in[1];
    const void*  bat      = d_in[2];
    const float* W_conv   = (const float*)d_in[3];
    const float* b_conv   = (const float*)d_in[4];
    const float* bn_gamma = (const float*)d_in[5];
    const float* bn_beta  = (const float*)d_in[6];
    const float* bn_mean  = (const float*)d_in[7];
    const float* bn_var   = (const float*)d_in[8];
    const float* W_fc1    = (const float*)d_in[9];
    const float* b_fc1    = (const float*)d_in[10];
    const float* W_fc2    = (const float*)d_in[11];
    const float* b_fc2    = (const float*)d_in[12];
    float* out = (float*)d_out;

    k_init<<<(N_NODES + 255) / 256, 256>>>((const int*)ei);
    k_edge<<<(E_EDGES + 255) / 256, 256>>>(ei);
    k_scan1<<<NB_SCAN, 256>>>();
    k_scan2<<<1, 512>>>();
    k_scan3<<<(N_NODES + 255) / 256, 256>>>();
    k_place<<<(E_EDGES + 255) / 256, 256>>>();
    k_fold_w<<<(3 * 8192 + 255) / 256, 256>>>(W_conv, bn_gamma, bn_var);
    k_fold_b<<<2, 256>>>(b_conv, bn_gamma, bn_beta, bn_mean, bn_var);

    for (int l = 0; l < 3; l++) {
        k_gemm<<<(N_NODES + 31) / 32, 256>>>(x, l - 1, l, (l > 0) ? 1 : 0);
        k_aggr<<<(N_NODES * 32 + 255) / 256, 256>>>(l);
    }

    k_batch<<<(N_NODES + 255) / 256, 256>>>(bat);
    dim3 pg(GG, 3);
    k_pool<<<pg, 128>>>();
    k_head<<<GG, 128>>>(W_fc1, b_fc1, W_fc2, b_fc2, out);
}

// round 10
// speedup vs baseline: 1.5843x; 1.0902x over previous
#include <cuda_runtime.h>
#include <cuda_fp16.h>
#include <cuda_fp8.h>

#define N_NODES 100000
#define E_EDGES 3200000
#define HIDF    128
#define GG      64
#define BN_EPS  1e-5f
#define NB_SCAN 391   // ceil(N_NODES/256)
#define TSCALE  16.0f
#define INV_TSCALE (1.0f / 16.0f)

// ---------------- static device scratch (no runtime allocations) -------------
__device__ int   g_is64;                          // 1 if index inputs are int64
__device__ float g_dis[N_NODES];                  // rsqrt(degree)
__device__ int   g_hist[N_NODES];                 // in-degree (excl self-loop)
__device__ int   g_off[N_NODES];                  // exclusive prefix of hist
__device__ int   g_cursor[N_NODES];               // placement cursors
__device__ int   g_bsum[512];                     // block sums for scan
__device__ int   g_sidx[E_EDGES];                 // dest-sorted src indices
__device__ __align__(16) unsigned g_xf8[(size_t)N_NODES * 32];  // fp8: 16*dis[r]*xw[r]
__device__ __align__(16) __half g_hbuf[3u * N_NODES * HIDF];    // per-layer pre-ReLU (fp16)
__device__ __align__(16) float g_Wp[3 * 2 * 64 * 64];          // BN-folded weights
__device__ __align__(16) float g_bp[3 * HIDF];                 // BN-folded bias
__device__ float g_pooled[GG * 3 * HIDF];
__device__ int   g_cnt[GG];
__device__ int   g_start[GG];

// fp8x2 (e4m3) -> half2
static __device__ __forceinline__ __half2 fp8x2_to_h2(unsigned short v) {
    __half2_raw hr = __nv_cvt_fp8x2_to_halfraw2((__nv_fp8x2_storage_t)v, __NV_E4M3);
    return *reinterpret_cast<__half2*>(&hr);
}
// float2 -> fp8x2 (e4m3)
static __device__ __forceinline__ unsigned short f2_to_fp8x2(float a, float b) {
    return (unsigned short)__nv_cvt_float2_to_fp8x2(make_float2(a, b), __NV_SATFINITE, __NV_E4M3);
}

// ---------------- init + dtype detection ------------------------------------
__global__ void k_init(const int* __restrict__ ei32) {
    int i = blockIdx.x * blockDim.x + threadIdx.x;
    if (i < N_NODES) g_hist[i] = 0;
    if (i < GG) { g_cnt[i] = 0; g_start[i] = 0; }
    if (i == 0) {
        int odd_zero = 1;
        for (int k = 0; k < 64; k++)
            if (ei32[2 * k + 1] != 0) odd_zero = 0;
        g_is64 = odd_zero;   // int64 values < 2^31 have zero high words
    }
}

// histogram over destination (no row/col staging)
__global__ void k_edge(const void* __restrict__ eiv) {
    int e = blockIdx.x * blockDim.x + threadIdx.x;
    if (e >= E_EDGES) return;
    int c;
    if (g_is64) c = (int)((const long long*)eiv)[(size_t)E_EDGES + e];
    else        c = ((const int*)eiv)[E_EDGES + e];
    atomicAdd(&g_hist[c], 1);
}

// ---------------- scan level 1 (+ dis = rsqrt(deg+1)) ------------------------
__global__ void __launch_bounds__(256) k_scan1() {
    __shared__ int sh[256];
    int b = blockIdx.x, t = threadIdx.x;
    int i = b * 256 + t;
    int v = (i < N_NODES) ? g_hist[i] : 0;
    if (i < N_NODES) g_dis[i] = rsqrtf((float)(v + 1));
    sh[t] = v;
    __syncthreads();
    for (int o = 1; o < 256; o <<= 1) {
        int u = (t >= o) ? sh[t - o] : 0;
        __syncthreads();
        sh[t] += u;
        __syncthreads();
    }
    if (i < N_NODES) g_off[i] = sh[t] - v;       // exclusive within block
    if (t == 255) g_bsum[b] = sh[255];
}

__global__ void __launch_bounds__(512) k_scan2() {
    __shared__ int sh[512];
    int t = threadIdx.x;
    int v = (t < NB_SCAN) ? g_bsum[t] : 0;
    sh[t] = v;
    __syncthreads();
    for (int o = 1; o < 512; o <<= 1) {
        int u = (t >= o) ? sh[t - o] : 0;
        __syncthreads();
        sh[t] += u;
        __syncthreads();
    }
    if (t < NB_SCAN) g_bsum[t] = sh[t] - v;      // exclusive block offsets
}

__global__ void k_scan3() {
    int i = blockIdx.x * blockDim.x + threadIdx.x;
    if (i >= N_NODES) return;
    int o = g_off[i] + g_bsum[i >> 8];
    g_off[i] = o;
    g_cursor[i] = o;
}

// place src index into dest-sorted order (4B store per edge)
__global__ void k_place(const void* __restrict__ eiv) {
    int e = blockIdx.x * blockDim.x + threadIdx.x;
    if (e >= E_EDGES) return;
    int r, c;
    if (g_is64) {
        const long long* ei = (const long long*)eiv;
        r = (int)ei[e];
        c = (int)ei[(size_t)E_EDGES + e];
    } else {
        const int* ei = (const int*)eiv;
        r = ei[e];
        c = ei[E_EDGES + e];
    }
    int pos = atomicAdd(&g_cursor[c], 1);
    g_sidx[pos] = r;
}

// ---------------- BN folding -------------------------------------------------
__global__ void k_fold_w(const float* __restrict__ W, const float* __restrict__ gamma,
                         const float* __restrict__ var) {
    int idx = blockIdx.x * blockDim.x + threadIdx.x;
    if (idx >= 3 * 8192) return;
    int l = idx / 8192;
    int rem = idx - l * 8192;
    int p = rem / 4096;
    int j = rem & 63;
    int c = p * 64 + j;
    float sg = gamma[l * HIDF + c] * rsqrtf(var[l * HIDF + c] + BN_EPS);
    g_Wp[idx] = W[idx] * sg;
}

__global__ void k_fold_b(const float* __restrict__ b, const float* __restrict__ gamma,
                         const float* __restrict__ beta, const float* __restrict__ mean,
                         const float* __restrict__ var) {
    int idx = blockIdx.x * blockDim.x + threadIdx.x;
    if (idx >= 3 * HIDF) return;
    float sg = gamma[idx] * rsqrtf(var[idx] + BN_EPS);
    g_bp[idx] = b[idx] * sg + (beta[idx] - mean[idx] * sg);
}

// ---------------- block-diagonal GEMM -> fp8 table of 16*dis[r]*xw[r] --------
__global__ void __launch_bounds__(256) k_gemm(const float* __restrict__ x,
                                              int src_layer, int layer) {
    __shared__ float sW[8192];        // [2][64][64]
    __shared__ float sIn[32 * HIDF];  // 32 rows x 128
    int t = threadIdx.x;
    const float4* Wl4 = (const float4*)(g_Wp + layer * 8192);
#pragma unroll
    for (int i = 0; i < 8; i++) {
        int idx = t + i * 256;
        ((float4*)sW)[idx] = Wl4[idx];
    }
    int R0 = blockIdx.x * 32;
    if (src_layer < 0) {
#pragma unroll
        for (int i = 0; i < 4; i++) {
            int idx = t + i * 256;
            int r = idx >> 5;
            int c4 = idx & 31;
            float4 v = make_float4(0.f, 0.f, 0.f, 0.f);
            if (R0 + r < N_NODES) v = ((const float4*)x)[(size_t)(R0 + r) * 32 + c4];
            ((float4*)sIn)[idx] = v;
        }
    } else {
        const uint2* hb = reinterpret_cast<const uint2*>(
            g_hbuf + (size_t)src_layer * N_NODES * HIDF);
#pragma unroll
        for (int i = 0; i < 4; i++) {
            int idx = t + i * 256;
            int r = idx >> 5;
            int c4 = idx & 31;
            float4 v = make_float4(0.f, 0.f, 0.f, 0.f);
            if (R0 + r < N_NODES) {
                uint2 hw = hb[(size_t)(R0 + r) * 32 + c4];
                float2 f0 = __half22float2(*reinterpret_cast<__half2*>(&hw.x));
                float2 f1 = __half22float2(*reinterpret_cast<__half2*>(&hw.y));
                v = make_float4(fmaxf(f0.x, 0.f), fmaxf(f0.y, 0.f),
                                fmaxf(f1.x, 0.f), fmaxf(f1.y, 0.f));
            }
            ((float4*)sIn)[idx] = v;
        }
    }
    __syncthreads();

    int cg = t & 31;
    int rg = t >> 5;
    int p = cg >> 4;
    int c0 = cg * 4;
    int jn = c0 & 63;
    int r0 = rg * 4;
    float acc[4][4];
#pragma unroll
    for (int i = 0; i < 4; i++) { acc[i][0] = acc[i][1] = acc[i][2] = acc[i][3] = 0.f; }
    const float* sWp = sW + p * 4096;
    const float* sInp = sIn + p * 64;
#pragma unroll 4
    for (int k = 0; k < 64; k++) {
        float4 w = *(const float4*)(sWp + k * 64 + jn);
#pragma unroll
        for (int i = 0; i < 4; i++) {
            float a = sInp[(r0 + i) * HIDF + k];
            acc[i][0] += a * w.x; acc[i][1] += a * w.y;
            acc[i][2] += a * w.z; acc[i][3] += a * w.w;
        }
    }
#pragma unroll
    for (int i = 0; i < 4; i++) {
        int r = R0 + r0 + i;
        if (r < N_NODES) {
            float sc = TSCALE * g_dis[r];
            unsigned lo = f2_to_fp8x2(acc[i][0] * sc, acc[i][1] * sc);
            unsigned hi = f2_to_fp8x2(acc[i][2] * sc, acc[i][3] * sc);
            g_xf8[(size_t)r * 32 + cg] = lo | (hi << 16);
        }
    }
}

// ---------------- segmented sum: one warp per destination --------------------
// Table rows pre-scaled by 16*dis[r]; per edge: pure half2 adds. Final:
// out = dc/16 * acc + bias  (self row seeds acc -> dc^2 * xw self term).
__global__ void __launch_bounds__(256) k_aggr(int layer) {
    int node = (blockIdx.x * 256 + threadIdx.x) >> 5;
    if (node >= N_NODES) return;
    int lane = threadIdx.x & 31;
    int s0 = g_off[node];
    int s1 = (node + 1 < N_NODES) ? g_off[node + 1] : E_EDGES;

    const unsigned* __restrict__ xb = g_xf8 + lane;

    // seed with self row (self-loop)
    unsigned sw = xb[(size_t)node * 32];
    __half2 acc0 = fp8x2_to_h2((unsigned short)(sw & 0xffffu));
    __half2 acc1 = fp8x2_to_h2((unsigned short)(sw >> 16));

    for (int s = s0; s < s1; s += 32) {
        int idx = 0;
        if (s + lane < s1) idx = g_sidx[s + lane];
        int cnt = min(32, s1 - s);
        for (int j = 0; j < cnt; j++) {
            int r = __shfl_sync(0xffffffffu, idx, j);
            unsigned w = __ldg(xb + (size_t)r * 32);
            acc0 = __hadd2(acc0, fp8x2_to_h2((unsigned short)(w & 0xffffu)));
            acc1 = __hadd2(acc1, fp8x2_to_h2((unsigned short)(w >> 16)));
        }
    }

    float dcs = g_dis[node] * INV_TSCALE;
    float4 b = ((const float4*)g_bp)[layer * 32 + lane];
    float2 f0 = __half22float2(acc0);
    float2 f1 = __half22float2(acc1);
    float4 o;
    o.x = b.x + f0.x * dcs; o.y = b.y + f0.y * dcs;
    o.z = b.z + f1.x * dcs; o.w = b.w + f1.y * dcs;

    __half2 h0 = __floats2half2_rn(o.x, o.y);
    __half2 h1 = __floats2half2_rn(o.z, o.w);
    uint2 st;
    *reinterpret_cast<__half2*>(&st.x) = h0;
    *reinterpret_cast<__half2*>(&st.y) = h1;
    reinterpret_cast<uint2*>(g_hbuf + (size_t)layer * N_NODES * HIDF)[(size_t)node * 32 + lane] = st;
}

// ---------------- batch counts + segment starts (batch is sorted) ------------
__global__ void k_batch(const void* __restrict__ bv) {
    int i = blockIdx.x * blockDim.x + threadIdx.x;
    if (i >= N_NODES) return;
    int b, bp = -1;
    if (g_is64) {
        const long long* bb = (const long long*)bv;
        b = (int)bb[i];
        if (i > 0) bp = (int)bb[i - 1];
    } else {
        const int* bb = (const int*)bv;
        b = bb[i];
        if (i > 0) bp = bb[i - 1];
    }
    atomicAdd(&g_cnt[b], 1);
    if (i == 0 || bp != b) g_start[b] = i;
}

// ---------------- mean pool with lazy ReLU (fp16 hbuf) -----------------------
__global__ void __launch_bounds__(128) k_pool() {
    int g = blockIdx.x;
    int l = blockIdx.y;
    int t = threadIdx.x;
    int s = g_start[g];
    int n = g_cnt[g];
    const __half* base = g_hbuf + ((size_t)l * N_NODES + s) * HIDF + t;
    float acc = 0.f;
    for (int j = 0; j < n; j++) acc += fmaxf(__half2float(base[(size_t)j * HIDF]), 0.f);
    g_pooled[g * (3 * HIDF) + l * HIDF + t] = acc / fmaxf((float)n, 1.f);
}

// ---------------- MLP head + log_softmax -------------------------------------
__global__ void __launch_bounds__(128) k_head(const float* __restrict__ Wfc1,
                                              const float* __restrict__ bfc1,
                                              const float* __restrict__ Wfc2,
                                              const float* __restrict__ bfc2,
                                              float* __restrict__ out) {
    __shared__ float sP[3 * HIDF];
    __shared__ float sH[HIDF];
    __shared__ float sZ[2];
    int g = blockIdx.x;
    int t = threadIdx.x;
    for (int i = t; i < 3 * HIDF; i += 128) sP[i] = g_pooled[g * (3 * HIDF) + i];
    __syncthreads();
    float acc = bfc1[t];
#pragma unroll 8
    for (int k = 0; k < 3 * HIDF; k++) acc += sP[k] * Wfc1[k * HIDF + t];
    sH[t] = fmaxf(acc, 0.f);
    __syncthreads();
    if (t < 2) {
        float z = bfc2[t];
#pragma unroll 8
        for (int j = 0; j < HIDF; j++) z += sH[j] * Wfc2[j * 2 + t];
        sZ[t] = z;
    }
    __syncthreads();
    if (t == 0) {
        float z0 = sZ[0], z1 = sZ[1];
        float m = fmaxf(z0, z1);
        float lse = m + logf(expf(z0 - m) + expf(z1 - m));
        out[g * 2 + 0] = z0 - lse;
        out[g * 2 + 1] = z1 - lse;
    }
}

// ---------------- driver ------------------------------------------------------
extern "C" void kernel_launch(void* const* d_in, const int* in_sizes, int n_in,
                              void* d_out, int out_size) {
    const float* x        = (const float*)d_in[0];
    const void*  ei       = d_in[1];
    const void*  bat      = d_in[2];
    const float* W_conv   = (const float*)d_in[3];
    const float* b_conv   = (const float*)d_in[4];
    const float* bn_gamma = (const float*)d_in[5];
    const float* bn_beta  = (const float*)d_in[6];
    const float* bn_mean  = (const float*)d_in[7];
    const float* bn_var   = (const float*)d_in[8];
    const float* W_fc1    = (const float*)d_in[9];
    const float* b_fc1    = (const float*)d_in[10];
    const float* W_fc2    = (const float*)d_in[11];
    const float* b_fc2    = (const float*)d_in[12];
    float* out = (float*)d_out;

    k_init<<<(N_NODES + 255) / 256, 256>>>((const int*)ei);
    k_edge<<<(E_EDGES + 255) / 256, 256>>>(ei);
    k_scan1<<<NB_SCAN, 256>>>();
    k_scan2<<<1, 512>>>();
    k_scan3<<<(N_NODES + 255) / 256, 256>>>();
    k_place<<<(E_EDGES + 255) / 256, 256>>>(ei);
    k_fold_w<<<(3 * 8192 + 255) / 256, 256>>>(W_conv, bn_gamma, bn_var);
    k_fold_b<<<2, 256>>>(b_conv, bn_gamma, bn_beta, bn_mean, bn_var);

    for (int l = 0; l < 3; l++) {
        k_gemm<<<(N_NODES + 31) / 32, 256>>>(x, l - 1, l);
        k_aggr<<<(N_NODES * 32 + 255) / 256, 256>>>(l);
    }

    k_batch<<<(N_NODES + 255) / 256, 256>>>(bat);
    dim3 pg(GG, 3);
    k_pool<<<pg, 128>>>();
    k_head<<<GG, 128>>>(W_fc1, b_fc1, W_fc2, b_fc2, out);
}

// round 11
// speedup vs baseline: 1.7001x; 1.0731x over previous
#include <cuda_runtime.h>
#include <cuda_fp16.h>
#include <cuda_fp8.h>
#include <cstdint>

#define N_NODES 100000
#define E_EDGES 3200000
#define HIDF    128
#define GG      64
#define BN_EPS  1e-5f
#define NB_SCAN 391   // ceil(N_NODES/256)
#define TSCALE  16.0f
#define INV_TSCALE (1.0f / 16.0f)

// ---------------- static device scratch (no runtime allocations) -------------
__device__ int   g_is64;                          // 1 if index inputs are int64
__device__ float g_dis[N_NODES];                  // rsqrt(degree)
__device__ int   g_hist[N_NODES];                 // in-degree (excl self-loop)
__device__ int   g_off[N_NODES];                  // exclusive prefix of hist
__device__ int   g_cursor[N_NODES];               // placement cursors
__device__ int   g_bsum[512];                     // block sums for scan
__device__ int   g_sidx[E_EDGES];                 // dest-sorted src indices
__device__ __align__(16) unsigned g_xf8[(size_t)N_NODES * 32];  // fp8: 16*dis[r]*xw[r]
__device__ __align__(16) __half g_hbuf[3u * N_NODES * HIDF];    // per-layer pre-ReLU (fp16)
__device__ __align__(16) __half g_Wh[3 * 2 * 64 * 64];          // BN-folded weights (fp16)
__device__ __align__(16) float g_bp[3 * HIDF];                  // BN-folded bias
__device__ float g_pooled[GG * 3 * HIDF];
__device__ int   g_cnt[GG];
__device__ int   g_start[GG];

// fp8x2 (e4m3) -> half2
static __device__ __forceinline__ __half2 fp8x2_to_h2(unsigned short v) {
    __half2_raw hr = __nv_cvt_fp8x2_to_halfraw2((__nv_fp8x2_storage_t)v, __NV_E4M3);
    return *reinterpret_cast<__half2*>(&hr);
}
// float2 -> fp8x2 (e4m3)
static __device__ __forceinline__ unsigned short f2_to_fp8x2(float a, float b) {
    return (unsigned short)__nv_cvt_float2_to_fp8x2(make_float2(a, b), __NV_SATFINITE, __NV_E4M3);
}

// ---------------- init + dtype detection ------------------------------------
__global__ void k_init(const int* __restrict__ ei32) {
    int i = blockIdx.x * blockDim.x + threadIdx.x;
    if (i < N_NODES) g_hist[i] = 0;
    if (i < GG) { g_cnt[i] = 0; g_start[i] = 0; }
    if (i == 0) {
        int odd_zero = 1;
        for (int k = 0; k < 64; k++)
            if (ei32[2 * k + 1] != 0) odd_zero = 0;
        g_is64 = odd_zero;   // int64 values < 2^31 have zero high words
    }
}

// histogram over destination
__global__ void k_edge(const void* __restrict__ eiv) {
    int e = blockIdx.x * blockDim.x + threadIdx.x;
    if (e >= E_EDGES) return;
    int c;
    if (g_is64) c = (int)((const long long*)eiv)[(size_t)E_EDGES + e];
    else        c = ((const int*)eiv)[E_EDGES + e];
    atomicAdd(&g_hist[c], 1);
}

// ---------------- scan level 1 (+ dis = rsqrt(deg+1)) ------------------------
__global__ void __launch_bounds__(256) k_scan1() {
    __shared__ int sh[256];
    int b = blockIdx.x, t = threadIdx.x;
    int i = b * 256 + t;
    int v = (i < N_NODES) ? g_hist[i] : 0;
    if (i < N_NODES) g_dis[i] = rsqrtf((float)(v + 1));
    sh[t] = v;
    __syncthreads();
    for (int o = 1; o < 256; o <<= 1) {
        int u = (t >= o) ? sh[t - o] : 0;
        __syncthreads();
        sh[t] += u;
        __syncthreads();
    }
    if (i < N_NODES) g_off[i] = sh[t] - v;
    if (t == 255) g_bsum[b] = sh[255];
}

__global__ void __launch_bounds__(512) k_scan2() {
    __shared__ int sh[512];
    int t = threadIdx.x;
    int v = (t < NB_SCAN) ? g_bsum[t] : 0;
    sh[t] = v;
    __syncthreads();
    for (int o = 1; o < 512; o <<= 1) {
        int u = (t >= o) ? sh[t - o] : 0;
        __syncthreads();
        sh[t] += u;
        __syncthreads();
    }
    if (t < NB_SCAN) g_bsum[t] = sh[t] - v;
}

__global__ void k_scan3() {
    int i = blockIdx.x * blockDim.x + threadIdx.x;
    if (i >= N_NODES) return;
    int o = g_off[i] + g_bsum[i >> 8];
    g_off[i] = o;
    g_cursor[i] = o;
}

// place src index into dest-sorted order
__global__ void k_place(const void* __restrict__ eiv) {
    int e = blockIdx.x * blockDim.x + threadIdx.x;
    if (e >= E_EDGES) return;
    int r, c;
    if (g_is64) {
        const long long* ei = (const long long*)eiv;
        r = (int)ei[e];
        c = (int)ei[(size_t)E_EDGES + e];
    } else {
        const int* ei = (const int*)eiv;
        r = ei[e];
        c = ei[E_EDGES + e];
    }
    int pos = atomicAdd(&g_cursor[c], 1);
    g_sidx[pos] = r;
}

// ---------------- BN folding (weights -> fp16) -------------------------------
__global__ void k_fold_w(const float* __restrict__ W, const float* __restrict__ gamma,
                         const float* __restrict__ var) {
    int idx = blockIdx.x * blockDim.x + threadIdx.x;
    if (idx >= 3 * 8192) return;
    int l = idx / 8192;
    int rem = idx - l * 8192;
    int p = rem / 4096;
    int j = rem & 63;
    int c = p * 64 + j;
    float sg = gamma[l * HIDF + c] * rsqrtf(var[l * HIDF + c] + BN_EPS);
    g_Wh[idx] = __float2half(W[idx] * sg);
}

__global__ void k_fold_b(const float* __restrict__ b, const float* __restrict__ gamma,
                         const float* __restrict__ beta, const float* __restrict__ mean,
                         const float* __restrict__ var) {
    int idx = blockIdx.x * blockDim.x + threadIdx.x;
    if (idx >= 3 * HIDF) return;
    float sg = gamma[idx] * rsqrtf(var[idx] + BN_EPS);
    g_bp[idx] = b[idx] * sg + (beta[idx] - mean[idx] * sg);
}

// ---------------- tensor-core block-diagonal GEMM -> fp8 table ---------------
// Block: 256 thr = 8 warps; covers 64 node rows. Warp w: part = w&1,
// rows = R0 + (w>>1)*16. Per warp: 4 k-tiles x 8 n-tiles of mma.m16n8k16.
#define SA_LD 136   // 128 + 8 halves pad
#define SB_LD 72    // 64 + 8 halves pad
__global__ void __launch_bounds__(256) k_gemm(const float* __restrict__ x,
                                              int src_layer, int layer) {
    __shared__ __half sA[64 * SA_LD];
    __shared__ __half sB[2 * 64 * SB_LD];
    int t = threadIdx.x;
    int R0 = blockIdx.x * 64;

    // stage W (fp16, row-major [p][k][j])
    const __half* Wl = g_Wh + layer * 8192;
    for (int i = t; i < 8192; i += 256) {
        int p = i >> 12, k = (i >> 6) & 63, j = i & 63;
        sB[(p * 64 + k) * SB_LD + j] = Wl[i];
    }
    // stage A (64 rows x 128 feats, fp16)
    if (src_layer < 0) {
        for (int i = t; i < 2048; i += 256) {
            int r = i >> 5, c4 = i & 31;
            float4 v = make_float4(0.f, 0.f, 0.f, 0.f);
            if (R0 + r < N_NODES) v = ((const float4*)x)[(size_t)(R0 + r) * 32 + c4];
            __half* dst = sA + r * SA_LD + c4 * 4;
            dst[0] = __float2half(v.x); dst[1] = __float2half(v.y);
            dst[2] = __float2half(v.z); dst[3] = __float2half(v.w);
        }
    } else {
        const uint2* hb = reinterpret_cast<const uint2*>(
            g_hbuf + (size_t)src_layer * N_NODES * HIDF);
        const __half2 z2 = __floats2half2_rn(0.f, 0.f);
        for (int i = t; i < 2048; i += 256) {
            int r = i >> 5, c4 = i & 31;
            __half2 h0 = z2, h1 = z2;
            if (R0 + r < N_NODES) {
                uint2 hw = hb[(size_t)(R0 + r) * 32 + c4];
                h0 = __hmax2(*reinterpret_cast<__half2*>(&hw.x), z2);
                h1 = __hmax2(*reinterpret_cast<__half2*>(&hw.y), z2);
            }
            __half* dst = sA + r * SA_LD + c4 * 4;
            *reinterpret_cast<__half2*>(dst) = h0;
            *reinterpret_cast<__half2*>(dst + 2) = h1;
        }
    }
    __syncthreads();

    int w = t >> 5, lane = t & 31;
    int part = w & 1;
    int wr = (w >> 1) << 4;          // warp row base within block: 0/16/32/48
    int g = lane >> 2, tig = lane & 3;

    float d[8][4];
#pragma unroll
    for (int n = 0; n < 8; n++) { d[n][0] = d[n][1] = d[n][2] = d[n][3] = 0.f; }

    // A ldmatrix address (per k-tile): matrix sel from lane>>3
    int mrow = lane & 7;
    int msel = lane >> 3;
    int arow = wr + mrow + ((msel & 1) << 3);
    int acolb = part * 64 + ((msel >> 1) << 3);
    int brow_l = lane & 15;

#pragma unroll
    for (int kt = 0; kt < 4; kt++) {
        uint32_t a0, a1, a2, a3;
        uint32_t aaddr = (uint32_t)__cvta_generic_to_shared(
            sA + arow * SA_LD + acolb + kt * 16);
        asm volatile("ldmatrix.sync.aligned.m8n8.x4.shared.b16 {%0,%1,%2,%3}, [%4];"
                     : "=r"(a0), "=r"(a1), "=r"(a2), "=r"(a3) : "r"(aaddr));
#pragma unroll
        for (int nt = 0; nt < 8; nt++) {
            uint32_t b0, b1;
            uint32_t baddr = (uint32_t)__cvta_generic_to_shared(
                sB + (part * 64 + kt * 16 + brow_l) * SB_LD + nt * 8);
            asm volatile("ldmatrix.sync.aligned.m8n8.x2.trans.shared.b16 {%0,%1}, [%2];"
                         : "=r"(b0), "=r"(b1) : "r"(baddr));
            asm volatile("mma.sync.aligned.m16n8k16.row.col.f32.f16.f16.f32 "
                         "{%0,%1,%2,%3}, {%4,%5,%6,%7}, {%8,%9}, {%0,%1,%2,%3};"
                         : "+f"(d[nt][0]), "+f"(d[nt][1]), "+f"(d[nt][2]), "+f"(d[nt][3])
                         : "r"(a0), "r"(a1), "r"(a2), "r"(a3), "r"(b0), "r"(b1));
        }
    }

    // store fp8x2: thread holds cols {nt*8+2tig, +1} of rows (R0+wr+g) and (+8)
    int row0 = R0 + wr + g;
    int row1 = row0 + 8;
    unsigned short* xf16 = reinterpret_cast<unsigned short*>(g_xf8);
    if (row0 < N_NODES) {
        float sc = TSCALE * g_dis[row0];
#pragma unroll
        for (int nt = 0; nt < 8; nt++) {
            int cidx = part * 32 + nt * 4 + tig;   // ushort index within row (64 total)
            xf16[(size_t)row0 * 64 + cidx] = f2_to_fp8x2(d[nt][0] * sc, d[nt][1] * sc);
        }
    }
    if (row1 < N_NODES) {
        float sc = TSCALE * g_dis[row1];
#pragma unroll
        for (int nt = 0; nt < 8; nt++) {
            int cidx = part * 32 + nt * 4 + tig;
            xf16[(size_t)row1 * 64 + cidx] = f2_to_fp8x2(d[nt][2] * sc, d[nt][3] * sc);
        }
    }
}

// ---------------- segmented sum: one warp per destination (unchanged R10) ----
__global__ void __launch_bounds__(256) k_aggr(int layer) {
    int node = (blockIdx.x * 256 + threadIdx.x) >> 5;
    if (node >= N_NODES) return;
    int lane = threadIdx.x & 31;
    int s0 = g_off[node];
    int s1 = (node + 1 < N_NODES) ? g_off[node + 1] : E_EDGES;

    const unsigned* __restrict__ xb = g_xf8 + lane;

    unsigned sw = xb[(size_t)node * 32];
    __half2 acc0 = fp8x2_to_h2((unsigned short)(sw & 0xffffu));
    __half2 acc1 = fp8x2_to_h2((unsigned short)(sw >> 16));

    for (int s = s0; s < s1; s += 32) {
        int idx = 0;
        if (s + lane < s1) idx = g_sidx[s + lane];
        int cnt = min(32, s1 - s);
        for (int j = 0; j < cnt; j++) {
            int r = __shfl_sync(0xffffffffu, idx, j);
            unsigned wv = __ldg(xb + (size_t)r * 32);
            acc0 = __hadd2(acc0, fp8x2_to_h2((unsigned short)(wv & 0xffffu)));
            acc1 = __hadd2(acc1, fp8x2_to_h2((unsigned short)(wv >> 16)));
        }
    }

    float dcs = g_dis[node] * INV_TSCALE;
    float4 b = ((const float4*)g_bp)[layer * 32 + lane];
    float2 f0 = __half22float2(acc0);
    float2 f1 = __half22float2(acc1);
    float4 o;
    o.x = b.x + f0.x * dcs; o.y = b.y + f0.y * dcs;
    o.z = b.z + f1.x * dcs; o.w = b.w + f1.y * dcs;

    __half2 h0 = __floats2half2_rn(o.x, o.y);
    __half2 h1 = __floats2half2_rn(o.z, o.w);
    uint2 st;
    *reinterpret_cast<__half2*>(&st.x) = h0;
    *reinterpret_cast<__half2*>(&st.y) = h1;
    reinterpret_cast<uint2*>(g_hbuf + (size_t)layer * N_NODES * HIDF)[(size_t)node * 32 + lane] = st;
}

// ---------------- batch counts + segment starts ------------------------------
__global__ void k_batch(const void* __restrict__ bv) {
    int i = blockIdx.x * blockDim.x + threadIdx.x;
    if (i >= N_NODES) return;
    int b, bp = -1;
    if (g_is64) {
        const long long* bb = (const long long*)bv;
        b = (int)bb[i];
        if (i > 0) bp = (int)bb[i - 1];
    } else {
        const int* bb = (const int*)bv;
        b = bb[i];
        if (i > 0) bp = bb[i - 1];
    }
    atomicAdd(&g_cnt[b], 1);
    if (i == 0 || bp != b) g_start[b] = i;
}

// ---------------- mean pool with lazy ReLU (fp16 hbuf) -----------------------
__global__ void __launch_bounds__(128) k_pool() {
    int g = blockIdx.x;
    int l = blockIdx.y;
    int t = threadIdx.x;
    int s = g_start[g];
    int n = g_cnt[g];
    const __half* base = g_hbuf + ((size_t)l * N_NODES + s) * HIDF + t;
    float acc = 0.f;
    for (int j = 0; j < n; j++) acc += fmaxf(__half2float(base[(size_t)j * HIDF]), 0.f);
    g_pooled[g * (3 * HIDF) + l * HIDF + t] = acc / fmaxf((float)n, 1.f);
}

// ---------------- MLP head + log_softmax -------------------------------------
__global__ void __launch_bounds__(128) k_head(const float* __restrict__ Wfc1,
                                              const float* __restrict__ bfc1,
                                              const float* __restrict__ Wfc2,
                                              const float* __restrict__ bfc2,
                                              float* __restrict__ out) {
    __shared__ float sP[3 * HIDF];
    __shared__ float sH[HIDF];
    __shared__ float sZ[2];
    int g = blockIdx.x;
    int t = threadIdx.x;
    for (int i = t; i < 3 * HIDF; i += 128) sP[i] = g_pooled[g * (3 * HIDF) + i];
    __syncthreads();
    float acc = bfc1[t];
#pragma unroll 8
    for (int k = 0; k < 3 * HIDF; k++) acc += sP[k] * Wfc1[k * HIDF + t];
    sH[t] = fmaxf(acc, 0.f);
    __syncthreads();
    if (t < 2) {
        float z = bfc2[t];
#pragma unroll 8
        for (int j = 0; j < HIDF; j++) z += sH[j] * Wfc2[j * 2 + t];
        sZ[t] = z;
    }
    __syncthreads();
    if (t == 0) {
        float z0 = sZ[0], z1 = sZ[1];
        float m = fmaxf(z0, z1);
        float lse = m + logf(expf(z0 - m) + expf(z1 - m));
        out[g * 2 + 0] = z0 - lse;
        out[g * 2 + 1] = z1 - lse;
    }
}

// ---------------- driver ------------------------------------------------------
extern "C" void kernel_launch(void* const* d_in, const int* in_sizes, int n_in,
                              void* d_out, int out_size) {
    const float* x        = (const float*)d_in[0];
    const void*  ei       = d_in[1];
    const void*  bat      = d_in[2];
    const float* W_conv   = (const float*)d_in[3];
    const float* b_conv   = (const float*)d_in[4];
    const float* bn_gamma = (const float*)d_in[5];
    const float* bn_beta  = (const float*)d_in[6];
    const float* bn_mean  = (const float*)d_in[7];
    const float* bn_var   = (const float*)d_in[8];
    const float* W_fc1    = (const float*)d_in[9];
    const float* b_fc1    = (const float*)d_in[10];
    const float* W_fc2    = (const float*)d_in[11];
    const float* b_fc2    = (const float*)d_in[12];
    float* out = (float*)d_out;

    k_init<<<(N_NODES + 255) / 256, 256>>>((const int*)ei);
    k_edge<<<(E_EDGES + 255) / 256, 256>>>(ei);
    k_scan1<<<NB_SCAN, 256>>>();
    k_scan2<<<1, 512>>>();
    k_scan3<<<(N_NODES + 255) / 256, 256>>>();
    k_place<<<(E_EDGES + 255) / 256, 256>>>(ei);
    k_fold_w<<<(3 * 8192 + 255) / 256, 256>>>(W_conv, bn_gamma, bn_var);
    k_fold_b<<<2, 256>>>(b_conv, bn_gamma, bn_beta, bn_mean, bn_var);

    for (int l = 0; l < 3; l++) {
        k_gemm<<<(N_NODES + 63) / 64, 256>>>(x, l - 1, l);
        k_aggr<<<(N_NODES * 32 + 255) / 256, 256>>>(l);
    }

    k_batch<<<(N_NODES + 255) / 256, 256>>>(bat);
    dim3 pg(GG, 3);
    k_pool<<<pg, 128>>>();
    k_head<<<GG, 128>>>(W_fc1, b_fc1, W_fc2, b_fc2, out);
}

// round 12
// speedup vs baseline: 2.2143x; 1.3025x over previous
#include <cuda_runtime.h>
#include <cuda_fp16.h>
#include <cuda_fp8.h>
#include <cstdint>

#define N_NODES 100000
#define E_EDGES 3200000
#define HIDF    128
#define GG      64
#define BN_EPS  1e-5f
#define NB_SCAN 391   // ceil(N_NODES/256)
#define TSCALE  16.0f
#define INV_TSCALE (1.0f / 16.0f)
#define POOL_SPLIT 8

// ---------------- static device scratch (no runtime allocations) -------------
__device__ int   g_is64;
__device__ float g_dis[N_NODES];
__device__ int   g_hist[N_NODES];
__device__ int   g_off[N_NODES];
__device__ int   g_cursor[N_NODES];
__device__ int   g_bsum[512];
__device__ int   g_sidx[E_EDGES];
__device__ __align__(16) unsigned g_xf8[((size_t)N_NODES + 1) * 32]; // fp8 table + zero dummy row
__device__ __align__(16) __half g_hbuf[3u * N_NODES * HIDF];
__device__ __align__(16) __half g_Wh[3 * 2 * 64 * 64];
__device__ __align__(16) float g_bp[3 * HIDF];
__device__ float g_pooled[GG * 3 * HIDF];
__device__ int   g_cnt[GG];
__device__ int   g_start[GG];

static __device__ __forceinline__ __half2 fp8x2_to_h2(unsigned short v) {
    __half2_raw hr = __nv_cvt_fp8x2_to_halfraw2((__nv_fp8x2_storage_t)v, __NV_E4M3);
    return *reinterpret_cast<__half2*>(&hr);
}
static __device__ __forceinline__ unsigned short f2_to_fp8x2(float a, float b) {
    return (unsigned short)__nv_cvt_float2_to_fp8x2(make_float2(a, b), __NV_SATFINITE, __NV_E4M3);
}

// ---------------- init + dtype detection + zeroing ---------------------------
__global__ void k_init(const int* __restrict__ ei32) {
    int i = blockIdx.x * blockDim.x + threadIdx.x;
    if (i < N_NODES) g_hist[i] = 0;
    if (i < GG) { g_cnt[i] = 0; g_start[i] = 0; }
    if (i < GG * 3 * HIDF) g_pooled[i] = 0.f;
    if (i < 32) g_xf8[(size_t)N_NODES * 32 + i] = 0u;   // dummy zero row
    if (i == 0) {
        int odd_zero = 1;
        for (int k = 0; k < 64; k++)
            if (ei32[2 * k + 1] != 0) odd_zero = 0;
        g_is64 = odd_zero;
    }
}

// histogram over destination
__global__ void k_edge(const void* __restrict__ eiv) {
    int e = blockIdx.x * blockDim.x + threadIdx.x;
    if (e >= E_EDGES) return;
    int c;
    if (g_is64) c = (int)((const long long*)eiv)[(size_t)E_EDGES + e];
    else        c = ((const int*)eiv)[E_EDGES + e];
    atomicAdd(&g_hist[c], 1);
}

// ---------------- scans ------------------------------------------------------
__global__ void __launch_bounds__(256) k_scan1() {
    __shared__ int sh[256];
    int b = blockIdx.x, t = threadIdx.x;
    int i = b * 256 + t;
    int v = (i < N_NODES) ? g_hist[i] : 0;
    if (i < N_NODES) g_dis[i] = rsqrtf((float)(v + 1));
    sh[t] = v;
    __syncthreads();
    for (int o = 1; o < 256; o <<= 1) {
        int u = (t >= o) ? sh[t - o] : 0;
        __syncthreads();
        sh[t] += u;
        __syncthreads();
    }
    if (i < N_NODES) g_off[i] = sh[t] - v;
    if (t == 255) g_bsum[b] = sh[255];
}

__global__ void __launch_bounds__(512) k_scan2() {
    __shared__ int sh[512];
    int t = threadIdx.x;
    int v = (t < NB_SCAN) ? g_bsum[t] : 0;
    sh[t] = v;
    __syncthreads();
    for (int o = 1; o < 512; o <<= 1) {
        int u = (t >= o) ? sh[t - o] : 0;
        __syncthreads();
        sh[t] += u;
        __syncthreads();
    }
    if (t < NB_SCAN) g_bsum[t] = sh[t] - v;
}

__global__ void k_scan3() {
    int i = blockIdx.x * blockDim.x + threadIdx.x;
    if (i >= N_NODES) return;
    int o = g_off[i] + g_bsum[i >> 8];
    g_off[i] = o;
    g_cursor[i] = o;
}

// place src index into dest-sorted order
__global__ void k_place(const void* __restrict__ eiv) {
    int e = blockIdx.x * blockDim.x + threadIdx.x;
    if (e >= E_EDGES) return;
    int r, c;
    if (g_is64) {
        const long long* ei = (const long long*)eiv;
        r = (int)ei[e];
        c = (int)ei[(size_t)E_EDGES + e];
    } else {
        const int* ei = (const int*)eiv;
        r = ei[e];
        c = ei[E_EDGES + e];
    }
    int pos = atomicAdd(&g_cursor[c], 1);
    g_sidx[pos] = r;
}

// ---------------- BN folding (weights fp16 + bias), one kernel ---------------
__global__ void k_fold(const float* __restrict__ W, const float* __restrict__ b,
                       const float* __restrict__ gamma, const float* __restrict__ beta,
                       const float* __restrict__ mean, const float* __restrict__ var) {
    int idx = blockIdx.x * blockDim.x + threadIdx.x;
    if (idx < 3 * 8192) {
        int l = idx / 8192;
        int rem = idx - l * 8192;
        int p = rem / 4096;
        int j = rem & 63;
        int c = p * 64 + j;
        float sg = gamma[l * HIDF + c] * rsqrtf(var[l * HIDF + c] + BN_EPS);
        g_Wh[idx] = __float2half(W[idx] * sg);
    }
    if (idx < 3 * HIDF) {
        float sg = gamma[idx] * rsqrtf(var[idx] + BN_EPS);
        g_bp[idx] = b[idx] * sg + (beta[idx] - mean[idx] * sg);
    }
}

// ---------------- tensor-core block-diagonal GEMM -> fp8 table ---------------
#define SA_LD 136
#define SB_LD 72
__global__ void __launch_bounds__(256) k_gemm(const float* __restrict__ x,
                                              int src_layer, int layer) {
    __shared__ __half sA[64 * SA_LD];
    __shared__ __half sB[2 * 64 * SB_LD];
    int t = threadIdx.x;
    int R0 = blockIdx.x * 64;

    const __half* Wl = g_Wh + layer * 8192;
    for (int i = t; i < 8192; i += 256) {
        int p = i >> 12, k = (i >> 6) & 63, j = i & 63;
        sB[(p * 64 + k) * SB_LD + j] = Wl[i];
    }
    if (src_layer < 0) {
        for (int i = t; i < 2048; i += 256) {
            int r = i >> 5, c4 = i & 31;
            float4 v = make_float4(0.f, 0.f, 0.f, 0.f);
            if (R0 + r < N_NODES) v = ((const float4*)x)[(size_t)(R0 + r) * 32 + c4];
            __half* dst = sA + r * SA_LD + c4 * 4;
            dst[0] = __float2half(v.x); dst[1] = __float2half(v.y);
            dst[2] = __float2half(v.z); dst[3] = __float2half(v.w);
        }
    } else {
        const uint2* hb = reinterpret_cast<const uint2*>(
            g_hbuf + (size_t)src_layer * N_NODES * HIDF);
        const __half2 z2 = __floats2half2_rn(0.f, 0.f);
        for (int i = t; i < 2048; i += 256) {
            int r = i >> 5, c4 = i & 31;
            __half2 h0 = z2, h1 = z2;
            if (R0 + r < N_NODES) {
                uint2 hw = hb[(size_t)(R0 + r) * 32 + c4];
                h0 = __hmax2(*reinterpret_cast<__half2*>(&hw.x), z2);
                h1 = __hmax2(*reinterpret_cast<__half2*>(&hw.y), z2);
            }
            __half* dst = sA + r * SA_LD + c4 * 4;
            *reinterpret_cast<__half2*>(dst) = h0;
            *reinterpret_cast<__half2*>(dst + 2) = h1;
        }
    }
    __syncthreads();

    int w = t >> 5, lane = t & 31;
    int part = w & 1;
    int wr = (w >> 1) << 4;
    int g = lane >> 2, tig = lane & 3;

    float d[8][4];
#pragma unroll
    for (int n = 0; n < 8; n++) { d[n][0] = d[n][1] = d[n][2] = d[n][3] = 0.f; }

    int mrow = lane & 7;
    int msel = lane >> 3;
    int arow = wr + mrow + ((msel & 1) << 3);
    int acolb = part * 64 + ((msel >> 1) << 3);
    int brow_l = lane & 15;

#pragma unroll
    for (int kt = 0; kt < 4; kt++) {
        uint32_t a0, a1, a2, a3;
        uint32_t aaddr = (uint32_t)__cvta_generic_to_shared(
            sA + arow * SA_LD + acolb + kt * 16);
        asm volatile("ldmatrix.sync.aligned.m8n8.x4.shared.b16 {%0,%1,%2,%3}, [%4];"
                     : "=r"(a0), "=r"(a1), "=r"(a2), "=r"(a3) : "r"(aaddr));
#pragma unroll
        for (int nt = 0; nt < 8; nt++) {
            uint32_t b0, b1;
            uint32_t baddr = (uint32_t)__cvta_generic_to_shared(
                sB + (part * 64 + kt * 16 + brow_l) * SB_LD + nt * 8);
            asm volatile("ldmatrix.sync.aligned.m8n8.x2.trans.shared.b16 {%0,%1}, [%2];"
                         : "=r"(b0), "=r"(b1) : "r"(baddr));
            asm volatile("mma.sync.aligned.m16n8k16.row.col.f32.f16.f16.f32 "
                         "{%0,%1,%2,%3}, {%4,%5,%6,%7}, {%8,%9}, {%0,%1,%2,%3};"
                         : "+f"(d[nt][0]), "+f"(d[nt][1]), "+f"(d[nt][2]), "+f"(d[nt][3])
                         : "r"(a0), "r"(a1), "r"(a2), "r"(a3), "r"(b0), "r"(b1));
        }
    }

    int row0 = R0 + wr + g;
    int row1 = row0 + 8;
    unsigned short* xf16 = reinterpret_cast<unsigned short*>(g_xf8);
    if (row0 < N_NODES) {
        float sc = TSCALE * g_dis[row0];
#pragma unroll
        for (int nt = 0; nt < 8; nt++) {
            int cidx = part * 32 + nt * 4 + tig;
            xf16[(size_t)row0 * 64 + cidx] = f2_to_fp8x2(d[nt][0] * sc, d[nt][1] * sc);
        }
    }
    if (row1 < N_NODES) {
        float sc = TSCALE * g_dis[row1];
#pragma unroll
        for (int nt = 0; nt < 8; nt++) {
            int cidx = part * 32 + nt * 4 + tig;
            xf16[(size_t)row1 * 64 + cidx] = f2_to_fp8x2(d[nt][2] * sc, d[nt][3] * sc);
        }
    }
}

// ---------------- segmented sum: one warp per node, 2 edges/iter -------------
// Half-warp h handles edges 2j+h of each 32-edge chunk; lane loads uint2 (8B)
// of the 128B row. Out-of-range lanes use the zero dummy row N_NODES.
__global__ void __launch_bounds__(256) k_aggr(int layer) {
    int node = (blockIdx.x * 256 + threadIdx.x) >> 5;
    if (node >= N_NODES) return;
    int lane = threadIdx.x & 31;
    int lg = lane & 15;
    int half1 = lane >> 4;            // 0 or 1
    int s0 = g_off[node];
    int s1 = (node + 1 < N_NODES) ? g_off[node + 1] : E_EDGES;

    const uint2* __restrict__ xb2 = reinterpret_cast<const uint2*>(g_xf8);
    const __half2 z2 = __floats2half2_rn(0.f, 0.f);
    __half2 a0 = z2, a1 = z2, a2 = z2, a3 = z2;

    for (int s = s0; s < s1; s += 32) {
        int idx = N_NODES;                       // zero dummy row
        if (s + lane < s1) idx = g_sidx[s + lane];
        int cnt = min(32, s1 - s);
        int jmax = (cnt + 1) >> 1;
        for (int j = 0; j < jmax; j++) {
            int r = __shfl_sync(0xffffffffu, idx, 2 * j + half1);
            uint2 w = __ldg(xb2 + (size_t)r * 16 + lg);
            a0 = __hadd2(a0, fp8x2_to_h2((unsigned short)(w.x & 0xffffu)));
            a1 = __hadd2(a1, fp8x2_to_h2((unsigned short)(w.x >> 16)));
            a2 = __hadd2(a2, fp8x2_to_h2((unsigned short)(w.y & 0xffffu)));
            a3 = __hadd2(a3, fp8x2_to_h2((unsigned short)(w.y >> 16)));
        }
    }

    // combine the two half-warps (lane lg pairs with lane lg+16, same lg)
    a0 = __hadd2(a0, __shfl_xor_sync(0xffffffffu, a0, 16));
    a1 = __hadd2(a1, __shfl_xor_sync(0xffffffffu, a1, 16));
    a2 = __hadd2(a2, __shfl_xor_sync(0xffffffffu, a2, 16));
    a3 = __hadd2(a3, __shfl_xor_sync(0xffffffffu, a3, 16));

    if (half1 == 0) {
        // add self row (self-loop), then scale + bias, store fp16 row chunk
        uint2 sw = xb2[(size_t)node * 16 + lg];
        a0 = __hadd2(a0, fp8x2_to_h2((unsigned short)(sw.x & 0xffffu)));
        a1 = __hadd2(a1, fp8x2_to_h2((unsigned short)(sw.x >> 16)));
        a2 = __hadd2(a2, fp8x2_to_h2((unsigned short)(sw.y & 0xffffu)));
        a3 = __hadd2(a3, fp8x2_to_h2((unsigned short)(sw.y >> 16)));

        float dcs = g_dis[node] * INV_TSCALE;
        const float4* bp4 = (const float4*)g_bp;
        float4 b0 = bp4[layer * 32 + lg * 2];
        float4 b1 = bp4[layer * 32 + lg * 2 + 1];
        float2 f0 = __half22float2(a0);
        float2 f1 = __half22float2(a1);
        float2 f2 = __half22float2(a2);
        float2 f3 = __half22float2(a3);
        __half2 o0 = __floats2half2_rn(b0.x + f0.x * dcs, b0.y + f0.y * dcs);
        __half2 o1 = __floats2half2_rn(b0.z + f1.x * dcs, b0.w + f1.y * dcs);
        __half2 o2 = __floats2half2_rn(b1.x + f2.x * dcs, b1.y + f2.y * dcs);
        __half2 o3 = __floats2half2_rn(b1.z + f3.x * dcs, b1.w + f3.y * dcs);
        uint4 st;
        *reinterpret_cast<__half2*>(&st.x) = o0;
        *reinterpret_cast<__half2*>(&st.y) = o1;
        *reinterpret_cast<__half2*>(&st.z) = o2;
        *reinterpret_cast<__half2*>(&st.w) = o3;
        reinterpret_cast<uint4*>(g_hbuf + (size_t)layer * N_NODES * HIDF)
            [(size_t)node * 16 + lg] = st;
    }
}

// ---------------- batch counts + segment starts ------------------------------
__global__ void k_batch(const void* __restrict__ bv) {
    int i = blockIdx.x * blockDim.x + threadIdx.x;
    if (i >= N_NODES) return;
    int b, bp = -1;
    if (g_is64) {
        const long long* bb = (const long long*)bv;
        b = (int)bb[i];
        if (i > 0) bp = (int)bb[i - 1];
    } else {
        const int* bb = (const int*)bv;
        b = bb[i];
        if (i > 0) bp = bb[i - 1];
    }
    atomicAdd(&g_cnt[b], 1);
    if (i == 0 || bp != b) g_start[b] = i;
}

// ---------------- mean pool: split + atomic partial sums ---------------------
__global__ void __launch_bounds__(128) k_pool() {
    int g = blockIdx.x;
    int l = blockIdx.y;
    int z = blockIdx.z;
    int t = threadIdx.x;
    int s = g_start[g];
    int n = g_cnt[g];
    int chunk = (n + POOL_SPLIT - 1) / POOL_SPLIT;
    int j0 = z * chunk;
    int j1 = min(n, j0 + chunk);
    if (j0 >= j1) return;
    const __half* base = g_hbuf + ((size_t)l * N_NODES + s) * HIDF + t;
    float acc = 0.f;
    for (int j = j0; j < j1; j++) acc += fmaxf(__half2float(base[(size_t)j * HIDF]), 0.f);
    atomicAdd(&g_pooled[g * (3 * HIDF) + l * HIDF + t], acc);
}

// ---------------- MLP head + log_softmax (divides pooled by count) -----------
__global__ void __launch_bounds__(128) k_head(const float* __restrict__ Wfc1,
                                              const float* __restrict__ bfc1,
                                              const float* __restrict__ Wfc2,
                                              const float* __restrict__ bfc2,
                                              float* __restrict__ out) {
    __shared__ float sP[3 * HIDF];
    __shared__ float sH[HIDF];
    __shared__ float sZ[2];
    int g = blockIdx.x;
    int t = threadIdx.x;
    float inv = 1.0f / fmaxf((float)g_cnt[g], 1.0f);
    for (int i = t; i < 3 * HIDF; i += 128) sP[i] = g_pooled[g * (3 * HIDF) + i] * inv;
    __syncthreads();
    float acc = bfc1[t];
#pragma unroll 8
    for (int k = 0; k < 3 * HIDF; k++) acc += sP[k] * Wfc1[k * HIDF + t];
    sH[t] = fmaxf(acc, 0.f);
    __syncthreads();
    if (t < 2) {
        float z = bfc2[t];
#pragma unroll 8
        for (int j = 0; j < HIDF; j++) z += sH[j] * Wfc2[j * 2 + t];
        sZ[t] = z;
    }
    __syncthreads();
    if (t == 0) {
        float z0 = sZ[0], z1 = sZ[1];
        float m = fmaxf(z0, z1);
        float lse = m + logf(expf(z0 - m) + expf(z1 - m));
        out[g * 2 + 0] = z0 - lse;
        out[g * 2 + 1] = z1 - lse;
    }
}

// ---------------- driver ------------------------------------------------------
extern "C" void kernel_launch(void* const* d_in, const int* in_sizes, int n_in,
                              void* d_out, int out_size) {
    const float* x        = (const float*)d_in[0];
    const void*  ei       = d_in[1];
    const void*  bat      = d_in[2];
    const float* W_conv   = (const float*)d_in[3];
    const float* b_conv   = (const float*)d_in[4];
    const float* bn_gamma = (const float*)d_in[5];
    const float* bn_beta  = (const float*)d_in[6];
    const float* bn_mean  = (const float*)d_in[7];
    const float* bn_var   = (const float*)d_in[8];
    const float* W_fc1    = (const float*)d_in[9];
    const float* b_fc1    = (const float*)d_in[10];
    const float* W_fc2    = (const float*)d_in[11];
    const float* b_fc2    = (const float*)d_in[12];
    float* out = (float*)d_out;

    k_init<<<(N_NODES + 255) / 256, 256>>>((const int*)ei);
    k_edge<<<(E_EDGES + 255) / 256, 256>>>(ei);
    k_scan1<<<NB_SCAN, 256>>>();
    k_scan2<<<1, 512>>>();
    k_scan3<<<(N_NODES + 255) / 256, 256>>>();
    k_place<<<(E_EDGES + 255) / 256, 256>>>(ei);
    k_fold<<<(3 * 8192 + 255) / 256, 256>>>(W_conv, b_conv, bn_gamma, bn_beta,
                                            bn_mean, bn_var);

    for (int l = 0; l < 3; l++) {
        k_gemm<<<(N_NODES + 63) / 64, 256>>>(x, l - 1, l);
        k_aggr<<<(N_NODES * 32 + 255) / 256, 256>>>(l);
    }

    k_batch<<<(N_NODES + 255) / 256, 256>>>(bat);
    dim3 pg(GG, 3, POOL_SPLIT);
    k_pool<<<pg, 128>>>();
    k_head<<<GG, 128>>>(W_fc1, b_fc1, W_fc2, b_fc2, out);
}